// round 4
// baseline (speedup 1.0000x reference)
#include <cuda_runtime.h>
#include <cstddef>

#define N_NODES 50000
#define N_EDGES 1600000
#define FEAT    1536
#define FH      768
#define HID     200
#define HB      400   /* both branches side by side */

#define SCAN_B  1024
#define SCAN_NB 49    /* ceil(50000/1024) */

/* ---------------- scratch (no allocations allowed) ---------------- */
__device__ float g_H  [(size_t)N_NODES * HB];   /* x @ W1  (80 MB)  */
__device__ float g_AGG[(size_t)N_NODES * HB];   /* layer-1 agg (80 MB) */
__device__ float g_Z  [N_NODES * 4];            /* h1 @ W2 (both branches) */
__device__ int   g_deg   [N_NODES];
__device__ int   g_off   [N_NODES + 1];
__device__ int   g_cursor[N_NODES];
__device__ int   g_srcs  [N_EDGES];
__device__ float g_ws    [N_EDGES];
__device__ int   g_bsum  [64];
__device__ int   g_carry [64];

/* ---------------- CSR build ---------------- */
__global__ void k_count(const int* __restrict__ dst) {
    int i = blockIdx.x * blockDim.x + threadIdx.x;
    if (i < N_EDGES) atomicAdd(&g_deg[dst[i]], 1);
}

__global__ void k_scan1() {
    __shared__ int sh[SCAN_B];
    int t = threadIdx.x, b = blockIdx.x;
    int i = b * SCAN_B + t;
    int v = (i < N_NODES) ? g_deg[i] : 0;
    sh[t] = v;
    __syncthreads();
    for (int s = 1; s < SCAN_B; s <<= 1) {
        int u = (t >= s) ? sh[t - s] : 0;
        __syncthreads();
        sh[t] += u;
        __syncthreads();
    }
    if (i < N_NODES) g_off[i + 1] = sh[t];
    if (t == SCAN_B - 1) g_bsum[b] = sh[t];
}

__global__ void k_scan2() {
    int acc = 0;
    for (int b = 0; b < SCAN_NB; ++b) { g_carry[b] = acc; acc += g_bsum[b]; }
}

__global__ void k_scan3() {
    int t = threadIdx.x, b = blockIdx.x;
    int i = b * SCAN_B + t;
    if (i < N_NODES) g_off[i + 1] += g_carry[b];
    if (i == 0) g_off[0] = 0;
}

__global__ void k_fill(const int* __restrict__ src, const int* __restrict__ dst,
                       const float* __restrict__ w) {
    int i = blockIdx.x * blockDim.x + threadIdx.x;
    if (i < N_EDGES) {
        int d = dst[i];
        int p = atomicAdd(&g_cursor[d], 1);
        g_srcs[p] = src[i];
        g_ws[p]   = w[i];
    }
}

/* ---------------- GEMM:  H[:, br*200 .. +200] = x[:, br*768 .. +768] @ W1 ----------------
 * BM=64, BN=208 (covers 200 with padding), BK=16, 256 threads, 4x13 micro-tile.
 * Thread layout: row-index = tid & 15 (fast) so a warp spans 16 row-groups x 2 col-groups
 * -> per-warp distinct smem bytes/k-step = (64 A + 26 B)*4 = 360B for 1664 FMA (0.22 B/FMA).
 */
__global__ void __launch_bounds__(256) k_gemm(const float* __restrict__ x,
                                              const float* __restrict__ W1a,
                                              const float* __restrict__ W1b) {
    const int branch = blockIdx.y;
    const float* __restrict__ W = branch ? W1b : W1a;
    const int row0 = blockIdx.x * 64;

    __shared__ float As[16][68];    /* [k][m], padded stride to dodge store conflicts */
    __shared__ float Bs[16][208];   /* [k][n] */

    const int tid = threadIdx.x;
    const int rt  = tid & 15;       /* row group 0..15 -> rows rt*4..rt*4+3 */
    const int ct  = tid >> 4;       /* col group 0..15 -> cols ct*13..ct*13+12 */

    float acc[4][13];
#pragma unroll
    for (int i = 0; i < 4; ++i)
#pragma unroll
        for (int j = 0; j < 13; ++j) acc[i][j] = 0.f;

    const int lr = tid >> 2;        /* 0..63: row for A-tile load   */
    const int lk = (tid & 3) * 4;   /* 0,4,8,12: k-quad for A load  */
    const float* __restrict__ xb = x + (size_t)branch * FH;

    for (int kb = 0; kb < FH; kb += 16) {
        /* A tile: 64 rows x 16 k, one float4 per thread */
        {
            int r = row0 + lr;
            float4 av = make_float4(0.f, 0.f, 0.f, 0.f);
            if (r < N_NODES)
                av = *(const float4*)(xb + (size_t)r * FEAT + kb + lk);
            As[lk + 0][lr] = av.x;
            As[lk + 1][lr] = av.y;
            As[lk + 2][lr] = av.z;
            As[lk + 3][lr] = av.w;
        }
        /* B tile: 16 k x 208 n (zero-pad n>=200), 13 elems per thread */
#pragma unroll
        for (int s = 0; s < 13; ++s) {
            int i = tid + s * 256;
            int k = i / 208, n = i % 208;
            Bs[k][n] = (n < HID) ? W[(kb + k) * HID + n] : 0.f;
        }
        __syncthreads();

#pragma unroll
        for (int k = 0; k < 16; ++k) {
            float4 a = *(const float4*)(&As[k][rt * 4]);
            float bv[13];
#pragma unroll
            for (int j = 0; j < 13; ++j) bv[j] = Bs[k][ct * 13 + j];
#pragma unroll
            for (int j = 0; j < 13; ++j) {
                acc[0][j] += a.x * bv[j];
                acc[1][j] += a.y * bv[j];
                acc[2][j] += a.z * bv[j];
                acc[3][j] += a.w * bv[j];
            }
        }
        __syncthreads();
    }

#pragma unroll
    for (int i = 0; i < 4; ++i) {
        int r = row0 + rt * 4 + i;
        if (r < N_NODES) {
#pragma unroll
            for (int j = 0; j < 13; ++j) {
                int n = ct * 13 + j;
                if (n < HID)
                    g_H[(size_t)r * HB + branch * HID + n] = acc[i][j];
            }
        }
    }
}

/* ---------------- layer-1 SpMM: AGG[n,:] = sum_e w_e * H[src_e,:]  ----------------
 * warp per (node, 100-col chunk); lane owns one float4. Gather working set per
 * chunk = 20 MB -> L2 resident. No atomics.
 */
__global__ void __launch_bounds__(256) k_spmm() {
    int wid = threadIdx.x >> 5, lane = threadIdx.x & 31;
    int n = blockIdx.x * 8 + wid;
    if (n >= N_NODES) return;
    if (lane >= 25) return;                    /* 25 float4 = 100 cols */
    int cf = blockIdx.y * 25 + lane;           /* float4 column index  */

    const float4* __restrict__ H4 = (const float4*)g_H;
    float4 acc = make_float4(0.f, 0.f, 0.f, 0.f);
    int e0 = g_off[n], e1 = g_off[n + 1];
    for (int j = e0; j < e1; ++j) {
        int s  = __ldg(&g_srcs[j]);            /* broadcast across lanes */
        float w = __ldg(&g_ws[j]);
        float4 h = H4[(size_t)s * 100 + cf];
        acc.x += w * h.x;
        acc.y += w * h.y;
        acc.z += w * h.z;
        acc.w += w * h.w;
    }
    ((float4*)g_AGG)[(size_t)n * 100 + cf] = acc;
}

/* ---------------- bias + relu + tiny GEMM (200 -> 2) per branch ---------------- */
__global__ void __launch_bounds__(256) k_hidden(const float* __restrict__ b1a,
                                                const float* __restrict__ b1b,
                                                const float* __restrict__ W2a,
                                                const float* __restrict__ W2b) {
    int wid = threadIdx.x >> 5, lane = threadIdx.x & 31;
    int n = blockIdx.x * 4 + (wid >> 1);
    int branch = wid & 1;
    if (n >= N_NODES) return;
    const float* __restrict__ b1 = branch ? b1b : b1a;
    const float* __restrict__ W2 = branch ? W2b : W2a;
    const float* __restrict__ row = g_AGG + (size_t)n * HB + branch * HID;

    float z0 = 0.f, z1 = 0.f;
    for (int c = lane; c < HID; c += 32) {
        float v = row[c] + b1[c];
        v = fmaxf(v, 0.f);
        z0 += v * W2[c * 2 + 0];
        z1 += v * W2[c * 2 + 1];
    }
    for (int o = 16; o; o >>= 1) {
        z0 += __shfl_xor_sync(0xffffffffu, z0, o);
        z1 += __shfl_xor_sync(0xffffffffu, z1, o);
    }
    if (lane == 0) {
        g_Z[n * 4 + branch * 2 + 0] = z0;
        g_Z[n * 4 + branch * 2 + 1] = z1;
    }
}

/* ---------------- layer-2 SpMM (4 floats/edge) + softmax + vote merge ---------------- */
__global__ void __launch_bounds__(256) k_final(const float* __restrict__ b2a,
                                               const float* __restrict__ b2b,
                                               float* __restrict__ out) {
    int wid = threadIdx.x >> 5, lane = threadIdx.x & 31;
    int n = blockIdx.x * 8 + wid;
    if (n >= N_NODES) return;

    float s0 = 0.f, s1 = 0.f, s2 = 0.f, s3 = 0.f;
    int e0 = g_off[n], e1 = g_off[n + 1];
    const float4* __restrict__ Z4 = (const float4*)g_Z;
    for (int j = e0 + lane; j < e1; j += 32) {
        float w  = g_ws[j];
        float4 z = Z4[g_srcs[j]];
        s0 += w * z.x;
        s1 += w * z.y;
        s2 += w * z.z;
        s3 += w * z.w;
    }
    for (int o = 16; o; o >>= 1) {
        s0 += __shfl_xor_sync(0xffffffffu, s0, o);
        s1 += __shfl_xor_sync(0xffffffffu, s1, o);
        s2 += __shfl_xor_sync(0xffffffffu, s2, o);
        s3 += __shfl_xor_sync(0xffffffffu, s3, o);
    }
    if (lane == 0) {
        float za0 = s0 + b2a[0], za1 = s1 + b2a[1];
        float m  = fmaxf(za0, za1);
        float ea0 = __expf(za0 - m), ea1 = __expf(za1 - m);
        float ia  = 1.f / (ea0 + ea1);
        float pa0 = ea0 * ia, pa1 = ea1 * ia;

        float zb0 = s2 + b2b[0], zb1 = s3 + b2b[1];
        m = fmaxf(zb0, zb1);
        float eb0 = __expf(zb0 - m), eb1 = __expf(zb1 - m);
        float ib  = 1.f / (eb0 + eb1);
        float pb0 = eb0 * ib, pb1 = eb1 * ib;

        float v0 = fmaxf(pa0, pb0), v1 = fmaxf(pa1, pb1);
        float inv = 1.f / (v0 + v1);
        out[n * 2 + 0] = v0 * inv;
        out[n * 2 + 1] = v1 * inv;
    }
}

/* ---------------- launch ---------------- */
extern "C" void kernel_launch(void* const* d_in, const int* in_sizes, int n_in,
                              void* d_out, int out_size) {
    const float* x    = (const float*)d_in[0];
    const int*   esrc = (const int*)  d_in[1];
    const int*   edst = (const int*)  d_in[2];
    const float* ew   = (const float*)d_in[3];
    const float* W1a  = (const float*)d_in[4];
    const float* b1a  = (const float*)d_in[5];
    const float* W2a  = (const float*)d_in[6];
    const float* b2a  = (const float*)d_in[7];
    const float* W1b  = (const float*)d_in[8];
    const float* b1b  = (const float*)d_in[9];
    const float* W2b  = (const float*)d_in[10];
    const float* b2b  = (const float*)d_in[11];
    float* out = (float*)d_out;

    void *p_deg = nullptr, *p_off = nullptr, *p_cursor = nullptr;
    cudaGetSymbolAddress(&p_deg, g_deg);
    cudaGetSymbolAddress(&p_off, g_off);
    cudaGetSymbolAddress(&p_cursor, g_cursor);

    /* CSR build (per launch, deterministic work) */
    cudaMemsetAsync(p_deg, 0, N_NODES * sizeof(int), 0);
    k_count<<<(N_EDGES + 255) / 256, 256>>>(edst);
    k_scan1<<<SCAN_NB, SCAN_B>>>();
    k_scan2<<<1, 1>>>();
    k_scan3<<<SCAN_NB, SCAN_B>>>();
    cudaMemcpyAsync(p_cursor, p_off, N_NODES * sizeof(int),
                    cudaMemcpyDeviceToDevice, 0);
    k_fill<<<(N_EDGES + 255) / 256, 256>>>(esrc, edst, ew);

    /* dense layer 1 (both branches), then graph conv */
    k_gemm<<<dim3((N_NODES + 63) / 64, 2), 256>>>(x, W1a, W1b);
    k_spmm<<<dim3((N_NODES + 7) / 8, 4), 256>>>();

    /* layer 2 + vote */
    k_hidden<<<(N_NODES + 3) / 4, 256>>>(b1a, b1b, W2a, W2b);
    k_final<<<(N_NODES + 7) / 8, 256>>>(b2a, b2b, out);
}

// round 6
// speedup vs baseline: 2.0088x; 2.0088x over previous
#include <cuda_runtime.h>
#include <cuda_bf16.h>
#include <cstdint>
#include <cstddef>

#define N_NODES 50000
#define N_EDGES 1600000
#define FEAT    1536
#define FH      768
#define HID     200
#define HB      400
#define NPAD    208

#define SCAN_B  1024
#define SCAN_NB 49

/* ---------------- scratch ---------------- */
__device__ float g_H  [(size_t)N_NODES * HB];
__device__ float g_AGG[(size_t)N_NODES * HB];
__device__ float g_Z  [N_NODES * 4];
__device__ int   g_deg   [N_NODES];
__device__ int   g_off   [N_NODES + 1];
__device__ int   g_cursor[N_NODES];
__device__ int   g_srcs  [N_EDGES];
__device__ float g_ws    [N_EDGES];
__device__ int   g_bsum  [64];
__device__ int   g_carry [64];
/* pre-split, pre-transposed weights: [branch][n=208][k=768] bf16 */
__device__ __nv_bfloat16 g_Wh[2 * NPAD * FH];
__device__ __nv_bfloat16 g_Wl[2 * NPAD * FH];

/* ---------------- small PTX helpers ---------------- */
__device__ __forceinline__ uint32_t smem_u32(const void* p) {
    uint32_t a;
    asm("{ .reg .u64 t; cvta.to.shared.u64 t, %1; cvt.u32.u64 %0, t; }"
        : "=r"(a) : "l"(p));
    return a;
}
__device__ __forceinline__ void cp_async16(uint32_t dst, const void* src) {
    asm volatile("cp.async.cg.shared.global [%0], [%1], 16;"
                 :: "r"(dst), "l"(src) : "memory");
}
#define CP_COMMIT() asm volatile("cp.async.commit_group;" ::: "memory")
#define CP_WAIT0()  asm volatile("cp.async.wait_group 0;" ::: "memory")

__device__ __forceinline__ void ldsm_x4(uint32_t a, uint32_t& r0, uint32_t& r1,
                                        uint32_t& r2, uint32_t& r3) {
    asm volatile("ldmatrix.sync.aligned.m8n8.x4.shared.b16 {%0,%1,%2,%3}, [%4];"
                 : "=r"(r0), "=r"(r1), "=r"(r2), "=r"(r3) : "r"(a));
}
__device__ __forceinline__ void ldsm_x2(uint32_t a, uint32_t& r0, uint32_t& r1) {
    asm volatile("ldmatrix.sync.aligned.m8n8.x2.shared.b16 {%0,%1}, [%2];"
                 : "=r"(r0), "=r"(r1) : "r"(a));
}
__device__ __forceinline__ void mma_bf16(float* c, const uint32_t* a,
                                         uint32_t b0, uint32_t b1) {
    asm volatile(
        "mma.sync.aligned.m16n8k16.row.col.f32.bf16.bf16.f32 "
        "{%0,%1,%2,%3}, {%4,%5,%6,%7}, {%8,%9}, {%0,%1,%2,%3};"
        : "+f"(c[0]), "+f"(c[1]), "+f"(c[2]), "+f"(c[3])
        : "r"(a[0]), "r"(a[1]), "r"(a[2]), "r"(a[3]), "r"(b0), "r"(b1));
}

/* ---------------- CSR build ---------------- */
__global__ void k_count(const int* __restrict__ dst) {
    int i = blockIdx.x * blockDim.x + threadIdx.x;
    if (i < N_EDGES) atomicAdd(&g_deg[dst[i]], 1);
}
__global__ void k_scan1() {
    __shared__ int sh[SCAN_B];
    int t = threadIdx.x, b = blockIdx.x;
    int i = b * SCAN_B + t;
    int v = (i < N_NODES) ? g_deg[i] : 0;
    sh[t] = v;
    __syncthreads();
    for (int s = 1; s < SCAN_B; s <<= 1) {
        int u = (t >= s) ? sh[t - s] : 0;
        __syncthreads();
        sh[t] += u;
        __syncthreads();
    }
    if (i < N_NODES) g_off[i + 1] = sh[t];
    if (t == SCAN_B - 1) g_bsum[b] = sh[t];
}
__global__ void k_scan2() {
    int acc = 0;
    for (int b = 0; b < SCAN_NB; ++b) { g_carry[b] = acc; acc += g_bsum[b]; }
}
__global__ void k_scan3() {
    int t = threadIdx.x, b = blockIdx.x;
    int i = b * SCAN_B + t;
    if (i < N_NODES) g_off[i + 1] += g_carry[b];
    if (i == 0) g_off[0] = 0;
}
__global__ void k_fill(const int* __restrict__ src, const int* __restrict__ dst,
                       const float* __restrict__ w) {
    int i = blockIdx.x * blockDim.x + threadIdx.x;
    if (i < N_EDGES) {
        int d = dst[i];
        int p = atomicAdd(&g_cursor[d], 1);
        g_srcs[p] = src[i];
        g_ws[p]   = w[i];
    }
}

/* ---------------- weight prep: split fp32 W[k][n] -> bf16 hi/lo [n][k] ---------------- */
__global__ void k_wprep(const float* __restrict__ W1a, const float* __restrict__ W1b) {
    int idx = blockIdx.x * blockDim.x + threadIdx.x;
    if (idx >= 2 * NPAD * FH) return;
    int branch = idx / (NPAD * FH);
    int rem = idx - branch * NPAD * FH;
    int n = rem / FH, k = rem - n * FH;
    const float* W = branch ? W1b : W1a;
    float w = (n < HID) ? W[k * HID + n] : 0.f;
    __nv_bfloat16 hi = __float2bfloat16_rn(w);
    float lo = w - __bfloat162float(hi);
    g_Wh[idx] = hi;
    g_Wl[idx] = __float2bfloat16_rn(lo);
}

/* ---------------- mma.sync GEMM: H = x(:,768 slice) @ W1, split-bf16 ----------------
 * CTA tile M=128, N=208, BK=32 bf16-k per stage, double-buffered.
 * 8 warps: 4(M) x 2(N); warp tile 32 x 104 -> 2 x 13 m16n8 accum tiles.
 * A converted fp32->bf16 hi/lo in regs; B (pre-split) streamed via cp.async.
 * SMEM rows padded to 80B -> ldmatrix conflict-free (5r mod 8).
 */
#define A_ST  80
#define B_ST  80
#define ASZ   (128 * A_ST)           /* 10240 */
#define BSZ   (NPAD * B_ST)          /* 16640 */
#define OFF_AH(s) ((s) * 2 * ASZ)
#define OFF_AL(s) (OFF_AH(s) + ASZ)
#define OFF_BH(s) (4 * ASZ + (s) * 2 * BSZ)
#define OFF_BL(s) (OFF_BH(s) + BSZ)
#define GEMM_SMEM (4 * ASZ + 4 * BSZ)   /* 107520 B */

__global__ void __launch_bounds__(256) k_gemm_mma(const float* __restrict__ x) {
    extern __shared__ char smem[];
    const uint32_t sb = smem_u32(smem);
    const int tid  = threadIdx.x;
    const int wid  = tid >> 5, lane = tid & 31;
    const int wm   = wid >> 1;            /* 0..3: M sub-tile (32 rows) */
    const int wn   = wid & 1;             /* 0..1: N sub-tile (104 cols) */
    const int branch = blockIdx.y;
    const int row0 = blockIdx.x * 128;

    const __nv_bfloat16* __restrict__ Wh = g_Wh + (size_t)branch * NPAD * FH;
    const __nv_bfloat16* __restrict__ Wl = g_Wl + (size_t)branch * NPAD * FH;
    const float* __restrict__ xb = x + (size_t)branch * FH;

    float acc[2][13][4];
#pragma unroll
    for (int i = 0; i < 2; ++i)
#pragma unroll
        for (int j = 0; j < 13; ++j)
#pragma unroll
            for (int q = 0; q < 4; ++q) acc[i][j][q] = 0.f;

    /* A loader mapping: 2 threads per row, 4 float4 each */
    const int a_row = tid >> 1;                 /* 0..127 */
    const int a_kof = (tid & 1) * 16;           /* fp32 k offset within 32 */
    const int a_rg  = row0 + a_row;
    const bool a_ok = (a_rg < N_NODES);
    const float* a_src_base = xb + (size_t)a_rg * FEAT + a_kof;
    const uint32_t a_smem_byte = a_row * A_ST + a_kof * 2;

    /* B cp.async mapping: idx -> n-row, 16B chunk */
    auto issue_B = [&](int kb, int s) {
#pragma unroll
        for (int it = 0; it < 4; ++it) {
            int idx = tid + it * 256;
            if (idx < NPAD * 4) {
                int n = idx >> 2, c = idx & 3;
                uint32_t off = n * B_ST + c * 16;
                const char* sh = (const char*)(Wh + (size_t)n * FH + kb) + c * 16;
                const char* sl = (const char*)(Wl + (size_t)n * FH + kb) + c * 16;
                cp_async16(sb + OFF_BH(s) + off, sh);
                cp_async16(sb + OFF_BL(s) + off, sl);
            }
        }
        CP_COMMIT();
    };

    auto store_A = [&](const float4* v, int s) {
        char* ah = smem + OFF_AH(s) + a_smem_byte;
        char* al = smem + OFF_AL(s) + a_smem_byte;
#pragma unroll
        for (int i = 0; i < 4; ++i) {
            float4 f = v[i];
            float hx = __bfloat162float(__float2bfloat16_rn(f.x));
            float hy = __bfloat162float(__float2bfloat16_rn(f.y));
            float hz = __bfloat162float(__float2bfloat16_rn(f.z));
            float hw = __bfloat162float(__float2bfloat16_rn(f.w));
            __nv_bfloat162 h01 = __floats2bfloat162_rn(hx, hy);
            __nv_bfloat162 h23 = __floats2bfloat162_rn(hz, hw);
            __nv_bfloat162 l01 = __floats2bfloat162_rn(f.x - hx, f.y - hy);
            __nv_bfloat162 l23 = __floats2bfloat162_rn(f.z - hz, f.w - hw);
            *(uint2*)(ah + i * 8) = make_uint2(*(uint32_t*)&h01, *(uint32_t*)&h23);
            *(uint2*)(al + i * 8) = make_uint2(*(uint32_t*)&l01, *(uint32_t*)&l23);
        }
    };

    /* ldmatrix address precompute (lane-dependent parts) */
    /* A x4: row = base + (lane&7) + ((lane>>3)&1)*8 ; kbyte = ks*32 + ((lane>>4)&1)*16 */
    const uint32_t a_ld_row = (lane & 7) + ((lane >> 3) & 1) * 8;
    const uint32_t a_ld_kb  = ((lane >> 4) & 1) * 16;
    /* B x2: n = n0 + (lane&7) ; kbyte = ks*32 + ((lane>>3)&1)*8*2  (lanes 0-15 used) */
    const uint32_t b_ld_row = lane & 7;
    const uint32_t b_ld_kb  = ((lane >> 3) & 1) * 16;

    /* ---- prologue: stage 0 ---- */
    {
        float4 av[4];
#pragma unroll
        for (int i = 0; i < 4; ++i)
            av[i] = a_ok ? *(const float4*)(a_src_base + i * 4)
                         : make_float4(0.f, 0.f, 0.f, 0.f);
        issue_B(0, 0);
        store_A(av, 0);
        CP_WAIT0();
    }
    __syncthreads();

    for (int kb = 0; kb < 24; ++kb) {
        const int s = kb & 1;
        float4 av[4];
        const bool more = (kb < 23);
        if (more) {
#pragma unroll
            for (int i = 0; i < 4; ++i)
                av[i] = a_ok ? *(const float4*)(a_src_base + (kb + 1) * 32 + i * 4)
                             : make_float4(0.f, 0.f, 0.f, 0.f);
            issue_B((kb + 1) * 32, s ^ 1);
        }

        /* ---- compute on stage s ---- */
        const uint32_t baseAh = sb + OFF_AH(s);
        const uint32_t baseAl = sb + OFF_AL(s);
        const uint32_t baseBh = sb + OFF_BH(s);
        const uint32_t baseBl = sb + OFF_BL(s);
#pragma unroll
        for (int ks = 0; ks < 2; ++ks) {
            uint32_t ah[2][4], al[2][4];
#pragma unroll
            for (int mt = 0; mt < 2; ++mt) {
                uint32_t r = wm * 32 + mt * 16 + a_ld_row;
                uint32_t ab = r * A_ST + ks * 32 + a_ld_kb;
                ldsm_x4(baseAh + ab, ah[mt][0], ah[mt][1], ah[mt][2], ah[mt][3]);
                ldsm_x4(baseAl + ab, al[mt][0], al[mt][1], al[mt][2], al[mt][3]);
            }
#pragma unroll
            for (int nt = 0; nt < 13; ++nt) {
                uint32_t n = wn * 104 + nt * 8 + b_ld_row;
                uint32_t bb = n * B_ST + ks * 32 + b_ld_kb;
                uint32_t bh0, bh1, bl0, bl1;
                ldsm_x2(baseBh + bb, bh0, bh1);
                ldsm_x2(baseBl + bb, bl0, bl1);
                mma_bf16(acc[0][nt], ah[0], bh0, bh1);
                mma_bf16(acc[1][nt], ah[1], bh0, bh1);
                mma_bf16(acc[0][nt], al[0], bh0, bh1);
                mma_bf16(acc[1][nt], al[1], bh0, bh1);
                mma_bf16(acc[0][nt], ah[0], bl0, bl1);
                mma_bf16(acc[1][nt], ah[1], bl0, bl1);
            }
        }

        if (more) {
            store_A(av, s ^ 1);
            CP_WAIT0();
        }
        __syncthreads();
    }

    /* ---- epilogue: regs -> g_H ---- */
#pragma unroll
    for (int mt = 0; mt < 2; ++mt) {
        int r0g = row0 + wm * 32 + mt * 16 + (lane >> 2);
#pragma unroll
        for (int nt = 0; nt < 13; ++nt) {
            int col = wn * 104 + nt * 8 + (lane & 3) * 2;
            if (col < HID) {
                if (r0g < N_NODES)
                    *(float2*)(g_H + (size_t)r0g * HB + branch * HID + col) =
                        make_float2(acc[mt][nt][0], acc[mt][nt][1]);
                if (r0g + 8 < N_NODES)
                    *(float2*)(g_H + (size_t)(r0g + 8) * HB + branch * HID + col) =
                        make_float2(acc[mt][nt][2], acc[mt][nt][3]);
            }
        }
    }
}

/* ---------------- layer-1 SpMM ---------------- */
__global__ void __launch_bounds__(256) k_spmm() {
    int wid = threadIdx.x >> 5, lane = threadIdx.x & 31;
    int n = blockIdx.x * 8 + wid;
    if (n >= N_NODES) return;
    if (lane >= 25) return;
    int cf = blockIdx.y * 25 + lane;

    const float4* __restrict__ H4 = (const float4*)g_H;
    float4 acc = make_float4(0.f, 0.f, 0.f, 0.f);
    int e0 = g_off[n], e1 = g_off[n + 1];
    for (int j = e0; j < e1; ++j) {
        int s  = __ldg(&g_srcs[j]);
        float w = __ldg(&g_ws[j]);
        float4 h = H4[(size_t)s * 100 + cf];
        acc.x += w * h.x;
        acc.y += w * h.y;
        acc.z += w * h.z;
        acc.w += w * h.w;
    }
    ((float4*)g_AGG)[(size_t)n * 100 + cf] = acc;
}

/* ---------------- bias + relu + 200->2 ---------------- */
__global__ void __launch_bounds__(256) k_hidden(const float* __restrict__ b1a,
                                                const float* __restrict__ b1b,
                                                const float* __restrict__ W2a,
                                                const float* __restrict__ W2b) {
    int wid = threadIdx.x >> 5, lane = threadIdx.x & 31;
    int n = blockIdx.x * 4 + (wid >> 1);
    int branch = wid & 1;
    if (n >= N_NODES) return;
    const float* __restrict__ b1 = branch ? b1b : b1a;
    const float* __restrict__ W2 = branch ? W2b : W2a;
    const float* __restrict__ row = g_AGG + (size_t)n * HB + branch * HID;

    float z0 = 0.f, z1 = 0.f;
    for (int c = lane; c < HID; c += 32) {
        float v = fmaxf(row[c] + b1[c], 0.f);
        z0 += v * W2[c * 2 + 0];
        z1 += v * W2[c * 2 + 1];
    }
    for (int o = 16; o; o >>= 1) {
        z0 += __shfl_xor_sync(0xffffffffu, z0, o);
        z1 += __shfl_xor_sync(0xffffffffu, z1, o);
    }
    if (lane == 0) {
        g_Z[n * 4 + branch * 2 + 0] = z0;
        g_Z[n * 4 + branch * 2 + 1] = z1;
    }
}

/* ---------------- layer-2 SpMM + softmax + vote ---------------- */
__global__ void __launch_bounds__(256) k_final(const float* __restrict__ b2a,
                                               const float* __restrict__ b2b,
                                               float* __restrict__ out) {
    int wid = threadIdx.x >> 5, lane = threadIdx.x & 31;
    int n = blockIdx.x * 8 + wid;
    if (n >= N_NODES) return;

    float s0 = 0.f, s1 = 0.f, s2 = 0.f, s3 = 0.f;
    int e0 = g_off[n], e1 = g_off[n + 1];
    const float4* __restrict__ Z4 = (const float4*)g_Z;
    for (int j = e0 + lane; j < e1; j += 32) {
        float w  = g_ws[j];
        float4 z = Z4[g_srcs[j]];
        s0 += w * z.x;
        s1 += w * z.y;
        s2 += w * z.z;
        s3 += w * z.w;
    }
    for (int o = 16; o; o >>= 1) {
        s0 += __shfl_xor_sync(0xffffffffu, s0, o);
        s1 += __shfl_xor_sync(0xffffffffu, s1, o);
        s2 += __shfl_xor_sync(0xffffffffu, s2, o);
        s3 += __shfl_xor_sync(0xffffffffu, s3, o);
    }
    if (lane == 0) {
        float za0 = s0 + b2a[0], za1 = s1 + b2a[1];
        float m  = fmaxf(za0, za1);
        float ea0 = __expf(za0 - m), ea1 = __expf(za1 - m);
        float ia  = 1.f / (ea0 + ea1);
        float pa0 = ea0 * ia, pa1 = ea1 * ia;

        float zb0 = s2 + b2b[0], zb1 = s3 + b2b[1];
        m = fmaxf(zb0, zb1);
        float eb0 = __expf(zb0 - m), eb1 = __expf(zb1 - m);
        float ib  = 1.f / (eb0 + eb1);
        float pb0 = eb0 * ib, pb1 = eb1 * ib;

        float v0 = fmaxf(pa0, pb0), v1 = fmaxf(pa1, pb1);
        float inv = 1.f / (v0 + v1);
        out[n * 2 + 0] = v0 * inv;
        out[n * 2 + 1] = v1 * inv;
    }
}

/* ---------------- launch ---------------- */
extern "C" void kernel_launch(void* const* d_in, const int* in_sizes, int n_in,
                              void* d_out, int out_size) {
    const float* x    = (const float*)d_in[0];
    const int*   esrc = (const int*)  d_in[1];
    const int*   edst = (const int*)  d_in[2];
    const float* ew   = (const float*)d_in[3];
    const float* W1a  = (const float*)d_in[4];
    const float* b1a  = (const float*)d_in[5];
    const float* W2a  = (const float*)d_in[6];
    const float* b2a  = (const float*)d_in[7];
    const float* W1b  = (const float*)d_in[8];
    const float* b1b  = (const float*)d_in[9];
    const float* W2b  = (const float*)d_in[10];
    const float* b2b  = (const float*)d_in[11];
    float* out = (float*)d_out;

    void *p_deg = nullptr, *p_off = nullptr, *p_cursor = nullptr;
    cudaGetSymbolAddress(&p_deg, g_deg);
    cudaGetSymbolAddress(&p_off, g_off);
    cudaGetSymbolAddress(&p_cursor, g_cursor);

    cudaFuncSetAttribute(k_gemm_mma, cudaFuncAttributeMaxDynamicSharedMemorySize,
                         GEMM_SMEM);

    /* CSR build */
    cudaMemsetAsync(p_deg, 0, N_NODES * sizeof(int), 0);
    k_count<<<(N_EDGES + 255) / 256, 256>>>(edst);
    k_scan1<<<SCAN_NB, SCAN_B>>>();
    k_scan2<<<1, 1>>>();
    k_scan3<<<SCAN_NB, SCAN_B>>>();
    cudaMemcpyAsync(p_cursor, p_off, N_NODES * sizeof(int),
                    cudaMemcpyDeviceToDevice, 0);
    k_fill<<<(N_EDGES + 255) / 256, 256>>>(esrc, edst, ew);

    /* weight prep + tensor-core layer-1 GEMM (both branches) */
    k_wprep<<<(2 * NPAD * FH + 255) / 256, 256>>>(W1a, W1b);
    k_gemm_mma<<<dim3((N_NODES + 127) / 128, 2), 256, GEMM_SMEM>>>(x);

    k_spmm<<<dim3((N_NODES + 7) / 8, 4), 256>>>();
    k_hidden<<<(N_NODES + 3) / 4, 256>>>(b1a, b1b, W2a, W2b);
    k_final<<<(N_NODES + 7) / 8, 256>>>(b2a, b2b, out);
}

// round 8
// speedup vs baseline: 2.0325x; 1.0118x over previous
#include <cuda_runtime.h>
#include <cuda_bf16.h>
#include <cuda_fp16.h>
#include <cstdint>
#include <cstddef>

#define N_NODES 50000
#define N_EDGES 1600000
#define FEAT    1536
#define FH      768
#define HID     200
#define HB      400
#define NPAD    208

#define SCAN_B  1024
#define SCAN_NB 49

/* ---------------- scratch ---------------- */
__device__ __half g_Hh[(size_t)N_NODES * HB];   /* x @ W1 in fp16 (40 MB) */
__device__ float g_Z  [N_NODES * 4];
__device__ int   g_deg   [N_NODES];
__device__ int   g_off   [N_NODES + 1];
__device__ int   g_cursor[N_NODES];
__device__ int   g_srcs  [N_EDGES];
__device__ float g_ws    [N_EDGES];
__device__ int   g_bsum  [64];
__device__ int   g_carry [64];
/* pre-split, pre-transposed weights: [branch][n=208][k=768] bf16 */
__device__ __nv_bfloat16 g_Wh[2 * NPAD * FH];
__device__ __nv_bfloat16 g_Wl[2 * NPAD * FH];

/* ---------------- small PTX helpers ---------------- */
__device__ __forceinline__ uint32_t smem_u32(const void* p) {
    uint32_t a;
    asm("{ .reg .u64 t; cvta.to.shared.u64 t, %1; cvt.u32.u64 %0, t; }"
        : "=r"(a) : "l"(p));
    return a;
}
__device__ __forceinline__ void cp_async16(uint32_t dst, const void* src) {
    asm volatile("cp.async.cg.shared.global [%0], [%1], 16;"
                 :: "r"(dst), "l"(src) : "memory");
}
#define CP_COMMIT() asm volatile("cp.async.commit_group;" ::: "memory")
#define CP_WAIT0()  asm volatile("cp.async.wait_group 0;" ::: "memory")

__device__ __forceinline__ void ldsm_x4(uint32_t a, uint32_t& r0, uint32_t& r1,
                                        uint32_t& r2, uint32_t& r3) {
    asm volatile("ldmatrix.sync.aligned.m8n8.x4.shared.b16 {%0,%1,%2,%3}, [%4];"
                 : "=r"(r0), "=r"(r1), "=r"(r2), "=r"(r3) : "r"(a));
}
__device__ __forceinline__ void ldsm_x2(uint32_t a, uint32_t& r0, uint32_t& r1) {
    asm volatile("ldmatrix.sync.aligned.m8n8.x2.shared.b16 {%0,%1}, [%2];"
                 : "=r"(r0), "=r"(r1) : "r"(a));
}
__device__ __forceinline__ void mma_bf16(float* c, const uint32_t* a,
                                         uint32_t b0, uint32_t b1) {
    asm volatile(
        "mma.sync.aligned.m16n8k16.row.col.f32.bf16.bf16.f32 "
        "{%0,%1,%2,%3}, {%4,%5,%6,%7}, {%8,%9}, {%0,%1,%2,%3};"
        : "+f"(c[0]), "+f"(c[1]), "+f"(c[2]), "+f"(c[3])
        : "r"(a[0]), "r"(a[1]), "r"(a[2]), "r"(a[3]), "r"(b0), "r"(b1));
}

/* ---------------- CSR build ---------------- */
__global__ void k_count(const int* __restrict__ dst) {
    int i = blockIdx.x * blockDim.x + threadIdx.x;
    if (i < N_EDGES) atomicAdd(&g_deg[dst[i]], 1);
}
__global__ void k_scan1() {
    __shared__ int sh[SCAN_B];
    int t = threadIdx.x, b = blockIdx.x;
    int i = b * SCAN_B + t;
    int v = (i < N_NODES) ? g_deg[i] : 0;
    sh[t] = v;
    __syncthreads();
    for (int s = 1; s < SCAN_B; s <<= 1) {
        int u = (t >= s) ? sh[t - s] : 0;
        __syncthreads();
        sh[t] += u;
        __syncthreads();
    }
    if (i < N_NODES) g_off[i + 1] = sh[t];
    if (t == SCAN_B - 1) g_bsum[b] = sh[t];
}
__global__ void k_scan2() {
    int acc = 0;
    for (int b = 0; b < SCAN_NB; ++b) { g_carry[b] = acc; acc += g_bsum[b]; }
}
__global__ void k_scan3() {
    int t = threadIdx.x, b = blockIdx.x;
    int i = b * SCAN_B + t;
    if (i < N_NODES) g_off[i + 1] += g_carry[b];
    if (i == 0) g_off[0] = 0;
}
__global__ void k_fill(const int* __restrict__ src, const int* __restrict__ dst,
                       const float* __restrict__ w) {
    int i = blockIdx.x * blockDim.x + threadIdx.x;
    if (i < N_EDGES) {
        int d = dst[i];
        int p = atomicAdd(&g_cursor[d], 1);
        g_srcs[p] = src[i];
        g_ws[p]   = w[i];
    }
}

/* ---------------- weight prep: split fp32 W[k][n] -> bf16 hi/lo [n][k] ---------------- */
__global__ void k_wprep(const float* __restrict__ W1a, const float* __restrict__ W1b) {
    int idx = blockIdx.x * blockDim.x + threadIdx.x;
    if (idx >= 2 * NPAD * FH) return;
    int branch = idx / (NPAD * FH);
    int rem = idx - branch * NPAD * FH;
    int n = rem / FH, k = rem - n * FH;
    const float* W = branch ? W1b : W1a;
    float w = (n < HID) ? W[k * HID + n] : 0.f;
    __nv_bfloat16 hi = __float2bfloat16_rn(w);
    float lo = w - __bfloat162float(hi);
    g_Wh[idx] = hi;
    g_Wl[idx] = __float2bfloat16_rn(lo);
}

/* ---------------- mma.sync GEMM: H = x(:,768 slice) @ W1, split-bf16 ---------------- */
#define A_ST  80
#define B_ST  80
#define ASZ   (128 * A_ST)
#define BSZ   (NPAD * B_ST)
#define OFF_AH(s) ((s) * 2 * ASZ)
#define OFF_AL(s) (OFF_AH(s) + ASZ)
#define OFF_BH(s) (4 * ASZ + (s) * 2 * BSZ)
#define OFF_BL(s) (OFF_BH(s) + BSZ)
#define GEMM_SMEM (4 * ASZ + 4 * BSZ)

__global__ void __launch_bounds__(256) k_gemm_mma(const float* __restrict__ x) {
    extern __shared__ char smem[];
    const uint32_t sb = smem_u32(smem);
    const int tid  = threadIdx.x;
    const int wid  = tid >> 5, lane = tid & 31;
    const int wm   = wid >> 1;
    const int wn   = wid & 1;
    const int branch = blockIdx.y;
    const int row0 = blockIdx.x * 128;

    const __nv_bfloat16* __restrict__ Wh = g_Wh + (size_t)branch * NPAD * FH;
    const __nv_bfloat16* __restrict__ Wl = g_Wl + (size_t)branch * NPAD * FH;
    const float* __restrict__ xb = x + (size_t)branch * FH;

    float acc[2][13][4];
#pragma unroll
    for (int i = 0; i < 2; ++i)
#pragma unroll
        for (int j = 0; j < 13; ++j)
#pragma unroll
            for (int q = 0; q < 4; ++q) acc[i][j][q] = 0.f;

    const int a_row = tid >> 1;
    const int a_kof = (tid & 1) * 16;
    const int a_rg  = row0 + a_row;
    const bool a_ok = (a_rg < N_NODES);
    const float* a_src_base = xb + (size_t)a_rg * FEAT + a_kof;
    const uint32_t a_smem_byte = a_row * A_ST + a_kof * 2;

    auto issue_B = [&](int kb, int s) {
#pragma unroll
        for (int it = 0; it < 4; ++it) {
            int idx = tid + it * 256;
            if (idx < NPAD * 4) {
                int n = idx >> 2, c = idx & 3;
                uint32_t off = n * B_ST + c * 16;
                const char* sh = (const char*)(Wh + (size_t)n * FH + kb) + c * 16;
                const char* sl = (const char*)(Wl + (size_t)n * FH + kb) + c * 16;
                cp_async16(sb + OFF_BH(s) + off, sh);
                cp_async16(sb + OFF_BL(s) + off, sl);
            }
        }
        CP_COMMIT();
    };

    auto store_A = [&](const float4* v, int s) {
        char* ah = smem + OFF_AH(s) + a_smem_byte;
        char* al = smem + OFF_AL(s) + a_smem_byte;
#pragma unroll
        for (int i = 0; i < 4; ++i) {
            float4 f = v[i];
            float hx = __bfloat162float(__float2bfloat16_rn(f.x));
            float hy = __bfloat162float(__float2bfloat16_rn(f.y));
            float hz = __bfloat162float(__float2bfloat16_rn(f.z));
            float hw = __bfloat162float(__float2bfloat16_rn(f.w));
            __nv_bfloat162 h01 = __floats2bfloat162_rn(hx, hy);
            __nv_bfloat162 h23 = __floats2bfloat162_rn(hz, hw);
            __nv_bfloat162 l01 = __floats2bfloat162_rn(f.x - hx, f.y - hy);
            __nv_bfloat162 l23 = __floats2bfloat162_rn(f.z - hz, f.w - hw);
            *(uint2*)(ah + i * 8) = make_uint2(*(uint32_t*)&h01, *(uint32_t*)&h23);
            *(uint2*)(al + i * 8) = make_uint2(*(uint32_t*)&l01, *(uint32_t*)&l23);
        }
    };

    const uint32_t a_ld_row = (lane & 7) + ((lane >> 3) & 1) * 8;
    const uint32_t a_ld_kb  = ((lane >> 4) & 1) * 16;
    const uint32_t b_ld_row = lane & 7;
    const uint32_t b_ld_kb  = ((lane >> 3) & 1) * 16;

    {
        float4 av[4];
#pragma unroll
        for (int i = 0; i < 4; ++i)
            av[i] = a_ok ? *(const float4*)(a_src_base + i * 4)
                         : make_float4(0.f, 0.f, 0.f, 0.f);
        issue_B(0, 0);
        store_A(av, 0);
        CP_WAIT0();
    }
    __syncthreads();

    for (int kb = 0; kb < 24; ++kb) {
        const int s = kb & 1;
        float4 av[4];
        const bool more = (kb < 23);
        if (more) {
#pragma unroll
            for (int i = 0; i < 4; ++i)
                av[i] = a_ok ? *(const float4*)(a_src_base + (kb + 1) * 32 + i * 4)
                             : make_float4(0.f, 0.f, 0.f, 0.f);
            issue_B((kb + 1) * 32, s ^ 1);
        }

        const uint32_t baseAh = sb + OFF_AH(s);
        const uint32_t baseAl = sb + OFF_AL(s);
        const uint32_t baseBh = sb + OFF_BH(s);
        const uint32_t baseBl = sb + OFF_BL(s);
#pragma unroll
        for (int ks = 0; ks < 2; ++ks) {
            uint32_t ah[2][4], al[2][4];
#pragma unroll
            for (int mt = 0; mt < 2; ++mt) {
                uint32_t r = wm * 32 + mt * 16 + a_ld_row;
                uint32_t ab = r * A_ST + ks * 32 + a_ld_kb;
                ldsm_x4(baseAh + ab, ah[mt][0], ah[mt][1], ah[mt][2], ah[mt][3]);
                ldsm_x4(baseAl + ab, al[mt][0], al[mt][1], al[mt][2], al[mt][3]);
            }
#pragma unroll
            for (int nt = 0; nt < 13; ++nt) {
                uint32_t n = wn * 104 + nt * 8 + b_ld_row;
                uint32_t bb = n * B_ST + ks * 32 + b_ld_kb;
                uint32_t bh0, bh1, bl0, bl1;
                ldsm_x2(baseBh + bb, bh0, bh1);
                ldsm_x2(baseBl + bb, bl0, bl1);
                mma_bf16(acc[0][nt], ah[0], bh0, bh1);
                mma_bf16(acc[1][nt], ah[1], bh0, bh1);
                mma_bf16(acc[0][nt], al[0], bh0, bh1);
                mma_bf16(acc[1][nt], al[1], bh0, bh1);
                mma_bf16(acc[0][nt], ah[0], bl0, bl1);
                mma_bf16(acc[1][nt], ah[1], bl0, bl1);
            }
        }

        if (more) {
            store_A(av, s ^ 1);
            CP_WAIT0();
        }
        __syncthreads();
    }

    /* ---- epilogue: regs -> g_Hh (fp16) ---- */
#pragma unroll
    for (int mt = 0; mt < 2; ++mt) {
        int r0g = row0 + wm * 32 + mt * 16 + (lane >> 2);
#pragma unroll
        for (int nt = 0; nt < 13; ++nt) {
            int col = wn * 104 + nt * 8 + (lane & 3) * 2;
            if (col < HID) {
                __half2 h01 = __floats2half2_rn(acc[mt][nt][0], acc[mt][nt][1]);
                __half2 h23 = __floats2half2_rn(acc[mt][nt][2], acc[mt][nt][3]);
                if (r0g < N_NODES)
                    *(__half2*)(g_Hh + (size_t)r0g * HB + branch * HID + col) = h01;
                if (r0g + 8 < N_NODES)
                    *(__half2*)(g_Hh + (size_t)(r0g + 8) * HB + branch * HID + col) = h23;
            }
        }
    }
}

/* ---------------- fused layer-1 SpMM + bias + relu + 200->2 ----------------
 * One warp per node. 25 lanes x 16 cols cover the full 400-col fp16 H row.
 * Accumulate in fp32, then bias+relu+W2 dot in registers -> g_Z.
 */
__device__ __forceinline__ void acc8(float* a, uint4 p, float w) {
    const __half2* h = (const __half2*)&p;
#pragma unroll
    for (int i = 0; i < 4; ++i) {
        float2 f = __half22float2(h[i]);
        a[2 * i]     += w * f.x;
        a[2 * i + 1] += w * f.y;
    }
}

__global__ void __launch_bounds__(256) k_spmm_fused(const float* __restrict__ b1a,
                                                    const float* __restrict__ b1b,
                                                    const float* __restrict__ W2a,
                                                    const float* __restrict__ W2b) {
    const int wid = threadIdx.x >> 5, lane = threadIdx.x & 31;
    const int n = blockIdx.x * 8 + wid;
    if (n >= N_NODES) return;

    float acc[16];
#pragma unroll
    for (int i = 0; i < 16; ++i) acc[i] = 0.f;

    const int e0 = g_off[n], e1 = g_off[n + 1];
    const uint4* __restrict__ Hq = (const uint4*)g_Hh;   /* 50 uint4 per row */

    if (lane < 25) {
        const int base = lane * 2;
        int j = e0;
        for (; j + 1 < e1; j += 2) {
            int   s0 = __ldg(&g_srcs[j]);
            int   s1 = __ldg(&g_srcs[j + 1]);
            float w0 = __ldg(&g_ws[j]);
            float w1 = __ldg(&g_ws[j + 1]);
            uint4 p0 = Hq[(size_t)s0 * 50 + base];
            uint4 q0 = Hq[(size_t)s0 * 50 + base + 1];
            uint4 p1 = Hq[(size_t)s1 * 50 + base];
            uint4 q1 = Hq[(size_t)s1 * 50 + base + 1];
            acc8(acc,     p0, w0);
            acc8(acc + 8, q0, w0);
            acc8(acc,     p1, w1);
            acc8(acc + 8, q1, w1);
        }
        if (j < e1) {
            int   s0 = __ldg(&g_srcs[j]);
            float w0 = __ldg(&g_ws[j]);
            uint4 p0 = Hq[(size_t)s0 * 50 + base];
            uint4 q0 = Hq[(size_t)s0 * 50 + base + 1];
            acc8(acc,     p0, w0);
            acc8(acc + 8, q0, w0);
        }
    }

    /* epilogue: bias + relu + tiny GEMM in registers */
    float za0 = 0.f, za1 = 0.f, zb0 = 0.f, zb1 = 0.f;
    if (lane < 25) {
#pragma unroll
        for (int c = 0; c < 16; ++c) {
            int col = lane * 16 + c;
            bool bB = (col >= HID);
            int hid = bB ? col - HID : col;
            float v = acc[c] + __ldg(bB ? &b1b[hid] : &b1a[hid]);
            v = fmaxf(v, 0.f);
            const float* __restrict__ W2 = bB ? W2b : W2a;
            float w0 = __ldg(&W2[hid * 2 + 0]);
            float w1 = __ldg(&W2[hid * 2 + 1]);
            if (bB) { zb0 += v * w0; zb1 += v * w1; }
            else    { za0 += v * w0; za1 += v * w1; }
        }
    }
#pragma unroll
    for (int o = 16; o; o >>= 1) {
        za0 += __shfl_xor_sync(0xffffffffu, za0, o);
        za1 += __shfl_xor_sync(0xffffffffu, za1, o);
        zb0 += __shfl_xor_sync(0xffffffffu, zb0, o);
        zb1 += __shfl_xor_sync(0xffffffffu, zb1, o);
    }
    if (lane == 0) {
        g_Z[n * 4 + 0] = za0;
        g_Z[n * 4 + 1] = za1;
        g_Z[n * 4 + 2] = zb0;
        g_Z[n * 4 + 3] = zb1;
    }
}

/* ---------------- layer-2 SpMM + softmax + vote ---------------- */
__global__ void __launch_bounds__(256) k_final(const float* __restrict__ b2a,
                                               const float* __restrict__ b2b,
                                               float* __restrict__ out) {
    int wid = threadIdx.x >> 5, lane = threadIdx.x & 31;
    int n = blockIdx.x * 8 + wid;
    if (n >= N_NODES) return;

    float s0 = 0.f, s1 = 0.f, s2 = 0.f, s3 = 0.f;
    int e0 = g_off[n], e1 = g_off[n + 1];
    const float4* __restrict__ Z4 = (const float4*)g_Z;
    for (int j = e0 + lane; j < e1; j += 32) {
        float w  = g_ws[j];
        float4 z = Z4[g_srcs[j]];
        s0 += w * z.x;
        s1 += w * z.y;
        s2 += w * z.z;
        s3 += w * z.w;
    }
    for (int o = 16; o; o >>= 1) {
        s0 += __shfl_xor_sync(0xffffffffu, s0, o);
        s1 += __shfl_xor_sync(0xffffffffu, s1, o);
        s2 += __shfl_xor_sync(0xffffffffu, s2, o);
        s3 += __shfl_xor_sync(0xffffffffu, s3, o);
    }
    if (lane == 0) {
        float za0 = s0 + b2a[0], za1 = s1 + b2a[1];
        float m  = fmaxf(za0, za1);
        float ea0 = __expf(za0 - m), ea1 = __expf(za1 - m);
        float ia  = 1.f / (ea0 + ea1);
        float pa0 = ea0 * ia, pa1 = ea1 * ia;

        float zb0 = s2 + b2b[0], zb1 = s3 + b2b[1];
        m = fmaxf(zb0, zb1);
        float eb0 = __expf(zb0 - m), eb1 = __expf(zb1 - m);
        float ib  = 1.f / (eb0 + eb1);
        float pb0 = eb0 * ib, pb1 = eb1 * ib;

        float v0 = fmaxf(pa0, pb0), v1 = fmaxf(pa1, pb1);
        float inv = 1.f / (v0 + v1);
        out[n * 2 + 0] = v0 * inv;
        out[n * 2 + 1] = v1 * inv;
    }
}

/* ---------------- launch ---------------- */
extern "C" void kernel_launch(void* const* d_in, const int* in_sizes, int n_in,
                              void* d_out, int out_size) {
    const float* x    = (const float*)d_in[0];
    const int*   esrc = (const int*)  d_in[1];
    const int*   edst = (const int*)  d_in[2];
    const float* ew   = (const float*)d_in[3];
    const float* W1a  = (const float*)d_in[4];
    const float* b1a  = (const float*)d_in[5];
    const float* W2a  = (const float*)d_in[6];
    const float* b2a  = (const float*)d_in[7];
    const float* W1b  = (const float*)d_in[8];
    const float* b1b  = (const float*)d_in[9];
    const float* W2b  = (const float*)d_in[10];
    const float* b2b  = (const float*)d_in[11];
    float* out = (float*)d_out;

    void *p_deg = nullptr, *p_off = nullptr, *p_cursor = nullptr;
    cudaGetSymbolAddress(&p_deg, g_deg);
    cudaGetSymbolAddress(&p_off, g_off);
    cudaGetSymbolAddress(&p_cursor, g_cursor);

    cudaFuncSetAttribute(k_gemm_mma, cudaFuncAttributeMaxDynamicSharedMemorySize,
                         GEMM_SMEM);

    /* CSR build */
    cudaMemsetAsync(p_deg, 0, N_NODES * sizeof(int), 0);
    k_count<<<(N_EDGES + 255) / 256, 256>>>(edst);
    k_scan1<<<SCAN_NB, SCAN_B>>>();
    k_scan2<<<1, 1>>>();
    k_scan3<<<SCAN_NB, SCAN_B>>>();
    cudaMemcpyAsync(p_cursor, p_off, N_NODES * sizeof(int),
                    cudaMemcpyDeviceToDevice, 0);
    k_fill<<<(N_EDGES + 255) / 256, 256>>>(esrc, edst, ew);

    /* weight prep + tensor-core layer-1 GEMM (both branches) */
    k_wprep<<<(2 * NPAD * FH + 255) / 256, 256>>>(W1a, W1b);
    k_gemm_mma<<<dim3((N_NODES + 127) / 128, 2), 256, GEMM_SMEM>>>(x);

    /* fused graph conv + hidden layer, then layer-2 + vote */
    k_spmm_fused<<<(N_NODES + 7) / 8, 256>>>(b1a, b1b, W2a, W2b);
    k_final<<<(N_NODES + 7) / 8, 256>>>(b2a, b2b, out);
}

// round 9
// speedup vs baseline: 2.5946x; 1.2766x over previous
#include <cuda_runtime.h>
#include <cuda_bf16.h>
#include <cuda_fp16.h>
#include <cstdint>
#include <cstddef>

#define N_NODES 50000
#define N_EDGES 1600000
#define FEAT    1536
#define FH      768
#define HID     200
#define HB      400
#define NPAD    208

#define SCAN_B  1024
#define SCAN_NB 49

/* ---------------- scratch ---------------- */
__device__ __half g_Hh[(size_t)N_NODES * HB];   /* x @ W1 in fp16 (40 MB) */
__device__ float g_Z  [N_NODES * 4];
__device__ int   g_deg   [N_NODES];
__device__ int   g_off   [N_NODES + 1];
__device__ int   g_cursor[N_NODES];
__device__ int   g_srcs  [N_EDGES];
__device__ float g_ws    [N_EDGES];
__device__ int   g_bsum  [64];
__device__ int   g_carry [64];
/* pre-transposed fp16 weights: [branch][n=208][k=768] */
__device__ __half g_Wf[2 * NPAD * FH];

/* ---------------- small PTX helpers ---------------- */
__device__ __forceinline__ uint32_t smem_u32(const void* p) {
    uint32_t a;
    asm("{ .reg .u64 t; cvta.to.shared.u64 t, %1; cvt.u32.u64 %0, t; }"
        : "=r"(a) : "l"(p));
    return a;
}
__device__ __forceinline__ void cp_async16(uint32_t dst, const void* src) {
    asm volatile("cp.async.cg.shared.global [%0], [%1], 16;"
                 :: "r"(dst), "l"(src) : "memory");
}
#define CP_COMMIT() asm volatile("cp.async.commit_group;" ::: "memory")
#define CP_WAIT0()  asm volatile("cp.async.wait_group 0;" ::: "memory")

__device__ __forceinline__ void ldsm_x4(uint32_t a, uint32_t& r0, uint32_t& r1,
                                        uint32_t& r2, uint32_t& r3) {
    asm volatile("ldmatrix.sync.aligned.m8n8.x4.shared.b16 {%0,%1,%2,%3}, [%4];"
                 : "=r"(r0), "=r"(r1), "=r"(r2), "=r"(r3) : "r"(a));
}
__device__ __forceinline__ void ldsm_x2(uint32_t a, uint32_t& r0, uint32_t& r1) {
    asm volatile("ldmatrix.sync.aligned.m8n8.x2.shared.b16 {%0,%1}, [%2];"
                 : "=r"(r0), "=r"(r1) : "r"(a));
}
__device__ __forceinline__ void mma_f16(float* c, const uint32_t* a,
                                        uint32_t b0, uint32_t b1) {
    asm volatile(
        "mma.sync.aligned.m16n8k16.row.col.f32.f16.f16.f32 "
        "{%0,%1,%2,%3}, {%4,%5,%6,%7}, {%8,%9}, {%0,%1,%2,%3};"
        : "+f"(c[0]), "+f"(c[1]), "+f"(c[2]), "+f"(c[3])
        : "r"(a[0]), "r"(a[1]), "r"(a[2]), "r"(a[3]), "r"(b0), "r"(b1));
}

/* ---------------- CSR build ---------------- */
__global__ void k_count(const int* __restrict__ dst) {
    int i = blockIdx.x * blockDim.x + threadIdx.x;
    if (i < N_EDGES) atomicAdd(&g_deg[dst[i]], 1);
}
__global__ void k_scan1() {
    __shared__ int sh[SCAN_B];
    int t = threadIdx.x, b = blockIdx.x;
    int i = b * SCAN_B + t;
    int v = (i < N_NODES) ? g_deg[i] : 0;
    sh[t] = v;
    __syncthreads();
    for (int s = 1; s < SCAN_B; s <<= 1) {
        int u = (t >= s) ? sh[t - s] : 0;
        __syncthreads();
        sh[t] += u;
        __syncthreads();
    }
    if (i < N_NODES) g_off[i + 1] = sh[t];
    if (t == SCAN_B - 1) g_bsum[b] = sh[t];
}
__global__ void k_scan2() {
    int acc = 0;
    for (int b = 0; b < SCAN_NB; ++b) { g_carry[b] = acc; acc += g_bsum[b]; }
}
__global__ void k_scan3() {
    int t = threadIdx.x, b = blockIdx.x;
    int i = b * SCAN_B + t;
    if (i < N_NODES) g_off[i + 1] += g_carry[b];
    if (i == 0) g_off[0] = 0;
}
__global__ void k_fill(const int* __restrict__ src, const int* __restrict__ dst,
                       const float* __restrict__ w) {
    int i = blockIdx.x * blockDim.x + threadIdx.x;
    if (i < N_EDGES) {
        int d = dst[i];
        int p = atomicAdd(&g_cursor[d], 1);
        g_srcs[p] = src[i];
        g_ws[p]   = w[i];
    }
}

/* ---------------- weight prep: fp32 W[k][n] -> fp16 [n][k] ---------------- */
__global__ void k_wprep(const float* __restrict__ W1a, const float* __restrict__ W1b) {
    int idx = blockIdx.x * blockDim.x + threadIdx.x;
    if (idx >= 2 * NPAD * FH) return;
    int branch = idx / (NPAD * FH);
    int rem = idx - branch * NPAD * FH;
    int n = rem / FH, k = rem - n * FH;
    const float* W = branch ? W1b : W1a;
    float w = (n < HID) ? W[k * HID + n] : 0.f;
    g_Wf[idx] = __float2half_rn(w);
}

/* ---------------- mma.sync fp16 GEMM: H = x(:,768 slice) @ W1 ----------------
 * CTA tile M=128, N=208, BK=32 k per stage, double-buffered.
 * 8 warps: 4(M) x 2(N); warp tile 32 x 104 -> 2 x 13 m16n8 accum tiles.
 * A converted fp32->fp16 in regs; B (pre-converted) streamed via cp.async.
 * SMEM rows padded to 80B -> ldmatrix conflict-free.
 */
#define A_ST  80
#define B_ST  80
#define ASZ   (128 * A_ST)
#define BSZ   (NPAD * B_ST)
#define OFF_A(s) ((s) * ASZ)
#define OFF_B(s) (2 * ASZ + (s) * BSZ)
#define GEMM_SMEM (2 * ASZ + 2 * BSZ)   /* 53760 B */

__global__ void __launch_bounds__(256) k_gemm_mma(const float* __restrict__ x) {
    extern __shared__ char smem[];
    const uint32_t sb = smem_u32(smem);
    const int tid  = threadIdx.x;
    const int wid  = tid >> 5, lane = tid & 31;
    const int wm   = wid >> 1;
    const int wn   = wid & 1;
    const int branch = blockIdx.y;
    const int row0 = blockIdx.x * 128;

    const __half* __restrict__ Wf = g_Wf + (size_t)branch * NPAD * FH;
    const float* __restrict__ xb = x + (size_t)branch * FH;

    float acc[2][13][4];
#pragma unroll
    for (int i = 0; i < 2; ++i)
#pragma unroll
        for (int j = 0; j < 13; ++j)
#pragma unroll
            for (int q = 0; q < 4; ++q) acc[i][j][q] = 0.f;

    const int a_row = tid >> 1;
    const int a_kof = (tid & 1) * 16;
    const int a_rg  = row0 + a_row;
    const bool a_ok = (a_rg < N_NODES);
    const float* a_src_base = xb + (size_t)a_rg * FEAT + a_kof;
    const uint32_t a_smem_byte = a_row * A_ST + a_kof * 2;

    auto issue_B = [&](int kb, int s) {
#pragma unroll
        for (int it = 0; it < 4; ++it) {
            int idx = tid + it * 256;
            if (idx < NPAD * 4) {
                int n = idx >> 2, c = idx & 3;
                uint32_t off = n * B_ST + c * 16;
                const char* sg = (const char*)(Wf + (size_t)n * FH + kb) + c * 16;
                cp_async16(sb + OFF_B(s) + off, sg);
            }
        }
        CP_COMMIT();
    };

    auto store_A = [&](const float4* v, int s) {
        char* ah = smem + OFF_A(s) + a_smem_byte;
#pragma unroll
        for (int i = 0; i < 4; ++i) {
            float4 f = v[i];
            __half2 h01 = __floats2half2_rn(f.x, f.y);
            __half2 h23 = __floats2half2_rn(f.z, f.w);
            *(uint2*)(ah + i * 8) = make_uint2(*(uint32_t*)&h01, *(uint32_t*)&h23);
        }
    };

    const uint32_t a_ld_row = (lane & 7) + ((lane >> 3) & 1) * 8;
    const uint32_t a_ld_kb  = ((lane >> 4) & 1) * 16;
    const uint32_t b_ld_row = lane & 7;
    const uint32_t b_ld_kb  = ((lane >> 3) & 1) * 16;

    {
        float4 av[4];
#pragma unroll
        for (int i = 0; i < 4; ++i)
            av[i] = a_ok ? *(const float4*)(a_src_base + i * 4)
                         : make_float4(0.f, 0.f, 0.f, 0.f);
        issue_B(0, 0);
        store_A(av, 0);
        CP_WAIT0();
    }
    __syncthreads();

    for (int kb = 0; kb < 24; ++kb) {
        const int s = kb & 1;
        float4 av[4];
        const bool more = (kb < 23);
        if (more) {
#pragma unroll
            for (int i = 0; i < 4; ++i)
                av[i] = a_ok ? *(const float4*)(a_src_base + (kb + 1) * 32 + i * 4)
                             : make_float4(0.f, 0.f, 0.f, 0.f);
            issue_B((kb + 1) * 32, s ^ 1);
        }

        const uint32_t baseA = sb + OFF_A(s);
        const uint32_t baseB = sb + OFF_B(s);
#pragma unroll
        for (int ks = 0; ks < 2; ++ks) {
            uint32_t ah[2][4];
#pragma unroll
            for (int mt = 0; mt < 2; ++mt) {
                uint32_t r = wm * 32 + mt * 16 + a_ld_row;
                uint32_t ab = r * A_ST + ks * 32 + a_ld_kb;
                ldsm_x4(baseA + ab, ah[mt][0], ah[mt][1], ah[mt][2], ah[mt][3]);
            }
#pragma unroll
            for (int nt = 0; nt < 13; ++nt) {
                uint32_t n = wn * 104 + nt * 8 + b_ld_row;
                uint32_t bb = n * B_ST + ks * 32 + b_ld_kb;
                uint32_t b0, b1;
                ldsm_x2(baseB + bb, b0, b1);
                mma_f16(acc[0][nt], ah[0], b0, b1);
                mma_f16(acc[1][nt], ah[1], b0, b1);
            }
        }

        if (more) {
            store_A(av, s ^ 1);
            CP_WAIT0();
        }
        __syncthreads();
    }

    /* ---- epilogue: regs -> g_Hh (fp16) ---- */
#pragma unroll
    for (int mt = 0; mt < 2; ++mt) {
        int r0g = row0 + wm * 32 + mt * 16 + (lane >> 2);
#pragma unroll
        for (int nt = 0; nt < 13; ++nt) {
            int col = wn * 104 + nt * 8 + (lane & 3) * 2;
            if (col < HID) {
                __half2 h01 = __floats2half2_rn(acc[mt][nt][0], acc[mt][nt][1]);
                __half2 h23 = __floats2half2_rn(acc[mt][nt][2], acc[mt][nt][3]);
                if (r0g < N_NODES)
                    *(__half2*)(g_Hh + (size_t)r0g * HB + branch * HID + col) = h01;
                if (r0g + 8 < N_NODES)
                    *(__half2*)(g_Hh + (size_t)(r0g + 8) * HB + branch * HID + col) = h23;
            }
        }
    }
}

/* ---------------- fused layer-1 SpMM + bias + relu + 200->2 ---------------- */
__device__ __forceinline__ void acc8(float* a, uint4 p, float w) {
    const __half2* h = (const __half2*)&p;
#pragma unroll
    for (int i = 0; i < 4; ++i) {
        float2 f = __half22float2(h[i]);
        a[2 * i]     += w * f.x;
        a[2 * i + 1] += w * f.y;
    }
}

__global__ void __launch_bounds__(256) k_spmm_fused(const float* __restrict__ b1a,
                                                    const float* __restrict__ b1b,
                                                    const float* __restrict__ W2a,
                                                    const float* __restrict__ W2b) {
    const int wid = threadIdx.x >> 5, lane = threadIdx.x & 31;
    const int n = blockIdx.x * 8 + wid;
    if (n >= N_NODES) return;

    float acc[16];
#pragma unroll
    for (int i = 0; i < 16; ++i) acc[i] = 0.f;

    const int e0 = g_off[n], e1 = g_off[n + 1];
    const uint4* __restrict__ Hq = (const uint4*)g_Hh;

    if (lane < 25) {
        const int base = lane * 2;
        int j = e0;
        for (; j + 1 < e1; j += 2) {
            int   s0 = __ldg(&g_srcs[j]);
            int   s1 = __ldg(&g_srcs[j + 1]);
            float w0 = __ldg(&g_ws[j]);
            float w1 = __ldg(&g_ws[j + 1]);
            uint4 p0 = Hq[(size_t)s0 * 50 + base];
            uint4 q0 = Hq[(size_t)s0 * 50 + base + 1];
            uint4 p1 = Hq[(size_t)s1 * 50 + base];
            uint4 q1 = Hq[(size_t)s1 * 50 + base + 1];
            acc8(acc,     p0, w0);
            acc8(acc + 8, q0, w0);
            acc8(acc,     p1, w1);
            acc8(acc + 8, q1, w1);
        }
        if (j < e1) {
            int   s0 = __ldg(&g_srcs[j]);
            float w0 = __ldg(&g_ws[j]);
            uint4 p0 = Hq[(size_t)s0 * 50 + base];
            uint4 q0 = Hq[(size_t)s0 * 50 + base + 1];
            acc8(acc,     p0, w0);
            acc8(acc + 8, q0, w0);
        }
    }

    float za0 = 0.f, za1 = 0.f, zb0 = 0.f, zb1 = 0.f;
    if (lane < 25) {
#pragma unroll
        for (int c = 0; c < 16; ++c) {
            int col = lane * 16 + c;
            bool bB = (col >= HID);
            int hid = bB ? col - HID : col;
            float v = acc[c] + __ldg(bB ? &b1b[hid] : &b1a[hid]);
            v = fmaxf(v, 0.f);
            const float* __restrict__ W2 = bB ? W2b : W2a;
            float w0 = __ldg(&W2[hid * 2 + 0]);
            float w1 = __ldg(&W2[hid * 2 + 1]);
            if (bB) { zb0 += v * w0; zb1 += v * w1; }
            else    { za0 += v * w0; za1 += v * w1; }
        }
    }
#pragma unroll
    for (int o = 16; o; o >>= 1) {
        za0 += __shfl_xor_sync(0xffffffffu, za0, o);
        za1 += __shfl_xor_sync(0xffffffffu, za1, o);
        zb0 += __shfl_xor_sync(0xffffffffu, zb0, o);
        zb1 += __shfl_xor_sync(0xffffffffu, zb1, o);
    }
    if (lane == 0) {
        g_Z[n * 4 + 0] = za0;
        g_Z[n * 4 + 1] = za1;
        g_Z[n * 4 + 2] = zb0;
        g_Z[n * 4 + 3] = zb1;
    }
}

/* ---------------- layer-2 SpMM + softmax + vote ---------------- */
__global__ void __launch_bounds__(256) k_final(const float* __restrict__ b2a,
                                               const float* __restrict__ b2b,
                                               float* __restrict__ out) {
    int wid = threadIdx.x >> 5, lane = threadIdx.x & 31;
    int n = blockIdx.x * 8 + wid;
    if (n >= N_NODES) return;

    float s0 = 0.f, s1 = 0.f, s2 = 0.f, s3 = 0.f;
    int e0 = g_off[n], e1 = g_off[n + 1];
    const float4* __restrict__ Z4 = (const float4*)g_Z;
    for (int j = e0 + lane; j < e1; j += 32) {
        float w  = g_ws[j];
        float4 z = Z4[g_srcs[j]];
        s0 += w * z.x;
        s1 += w * z.y;
        s2 += w * z.z;
        s3 += w * z.w;
    }
    for (int o = 16; o; o >>= 1) {
        s0 += __shfl_xor_sync(0xffffffffu, s0, o);
        s1 += __shfl_xor_sync(0xffffffffu, s1, o);
        s2 += __shfl_xor_sync(0xffffffffu, s2, o);
        s3 += __shfl_xor_sync(0xffffffffu, s3, o);
    }
    if (lane == 0) {
        float za0 = s0 + b2a[0], za1 = s1 + b2a[1];
        float m  = fmaxf(za0, za1);
        float ea0 = __expf(za0 - m), ea1 = __expf(za1 - m);
        float ia  = 1.f / (ea0 + ea1);
        float pa0 = ea0 * ia, pa1 = ea1 * ia;

        float zb0 = s2 + b2b[0], zb1 = s3 + b2b[1];
        m = fmaxf(zb0, zb1);
        float eb0 = __expf(zb0 - m), eb1 = __expf(zb1 - m);
        float ib  = 1.f / (eb0 + eb1);
        float pb0 = eb0 * ib, pb1 = eb1 * ib;

        float v0 = fmaxf(pa0, pb0), v1 = fmaxf(pa1, pb1);
        float inv = 1.f / (v0 + v1);
        out[n * 2 + 0] = v0 * inv;
        out[n * 2 + 1] = v1 * inv;
    }
}

/* ---------------- launch ---------------- */
extern "C" void kernel_launch(void* const* d_in, const int* in_sizes, int n_in,
                              void* d_out, int out_size) {
    const float* x    = (const float*)d_in[0];
    const int*   esrc = (const int*)  d_in[1];
    const int*   edst = (const int*)  d_in[2];
    const float* ew   = (const float*)d_in[3];
    const float* W1a  = (const float*)d_in[4];
    const float* b1a  = (const float*)d_in[5];
    const float* W2a  = (const float*)d_in[6];
    const float* b2a  = (const float*)d_in[7];
    const float* W1b  = (const float*)d_in[8];
    const float* b1b  = (const float*)d_in[9];
    const float* W2b  = (const float*)d_in[10];
    const float* b2b  = (const float*)d_in[11];
    float* out = (float*)d_out;

    void *p_deg = nullptr, *p_off = nullptr, *p_cursor = nullptr;
    cudaGetSymbolAddress(&p_deg, g_deg);
    cudaGetSymbolAddress(&p_off, g_off);
    cudaGetSymbolAddress(&p_cursor, g_cursor);

    cudaFuncSetAttribute(k_gemm_mma, cudaFuncAttributeMaxDynamicSharedMemorySize,
                         GEMM_SMEM);

    /* CSR build */
    cudaMemsetAsync(p_deg, 0, N_NODES * sizeof(int), 0);
    k_count<<<(N_EDGES + 255) / 256, 256>>>(edst);
    k_scan1<<<SCAN_NB, SCAN_B>>>();
    k_scan2<<<1, 1>>>();
    k_scan3<<<SCAN_NB, SCAN_B>>>();
    cudaMemcpyAsync(p_cursor, p_off, N_NODES * sizeof(int),
                    cudaMemcpyDeviceToDevice, 0);
    k_fill<<<(N_EDGES + 255) / 256, 256>>>(esrc, edst, ew);

    /* weight prep + tensor-core layer-1 GEMM (both branches) */
    k_wprep<<<(2 * NPAD * FH + 255) / 256, 256>>>(W1a, W1b);
    k_gemm_mma<<<dim3((N_NODES + 127) / 128, 2), 256, GEMM_SMEM>>>(x);

    /* fused graph conv + hidden layer, then layer-2 + vote */
    k_spmm_fused<<<(N_NODES + 7) / 8, 256>>>(b1a, b1b, W2a, W2b);
    k_final<<<(N_NODES + 7) / 8, 256>>>(b2a, b2b, out);
}

// round 10
// speedup vs baseline: 2.6128x; 1.0070x over previous
#include <cuda_runtime.h>
#include <cuda_bf16.h>
#include <cuda_fp16.h>
#include <cstdint>
#include <cstddef>

#define N_NODES 50000
#define N_EDGES 1600000
#define FEAT    1536
#define FH      768
#define HID     200
#define HB      400
#define NPAD    208

#define SCAN_B  1024
#define SCAN_NB 49

/* ---------------- scratch ---------------- */
__device__ __half g_Hh[(size_t)N_NODES * HB];   /* x @ W1 in fp16 (40 MB) */
__device__ float g_Z  [N_NODES * 4];
__device__ int   g_deg   [N_NODES];
__device__ int   g_off   [N_NODES + 1];
__device__ int   g_cursor[N_NODES];
__device__ uint2 g_edge  [N_EDGES];             /* packed (src, w) */
__device__ int   g_bsum  [64];
__device__ int   g_carry [64];
/* pre-transposed fp16 weights: [branch][n=208][k=768] */
__device__ __half g_Wf[2 * NPAD * FH];

/* ---------------- small PTX helpers ---------------- */
__device__ __forceinline__ uint32_t smem_u32(const void* p) {
    uint32_t a;
    asm("{ .reg .u64 t; cvta.to.shared.u64 t, %1; cvt.u32.u64 %0, t; }"
        : "=r"(a) : "l"(p));
    return a;
}
__device__ __forceinline__ void cp_async16(uint32_t dst, const void* src) {
    asm volatile("cp.async.cg.shared.global [%0], [%1], 16;"
                 :: "r"(dst), "l"(src) : "memory");
}
#define CP_COMMIT() asm volatile("cp.async.commit_group;" ::: "memory")
#define CP_WAIT0()  asm volatile("cp.async.wait_group 0;" ::: "memory")

__device__ __forceinline__ void ldsm_x4(uint32_t a, uint32_t& r0, uint32_t& r1,
                                        uint32_t& r2, uint32_t& r3) {
    asm volatile("ldmatrix.sync.aligned.m8n8.x4.shared.b16 {%0,%1,%2,%3}, [%4];"
                 : "=r"(r0), "=r"(r1), "=r"(r2), "=r"(r3) : "r"(a));
}
__device__ __forceinline__ void ldsm_x2(uint32_t a, uint32_t& r0, uint32_t& r1) {
    asm volatile("ldmatrix.sync.aligned.m8n8.x2.shared.b16 {%0,%1}, [%2];"
                 : "=r"(r0), "=r"(r1) : "r"(a));
}
__device__ __forceinline__ void mma_f16(float* c, const uint32_t* a,
                                        uint32_t b0, uint32_t b1) {
    asm volatile(
        "mma.sync.aligned.m16n8k16.row.col.f32.f16.f16.f32 "
        "{%0,%1,%2,%3}, {%4,%5,%6,%7}, {%8,%9}, {%0,%1,%2,%3};"
        : "+f"(c[0]), "+f"(c[1]), "+f"(c[2]), "+f"(c[3])
        : "r"(a[0]), "r"(a[1]), "r"(a[2]), "r"(a[3]), "r"(b0), "r"(b1));
}

/* ---------------- CSR build ---------------- */
__global__ void k_count(const int* __restrict__ dst) {
    int i = blockIdx.x * blockDim.x + threadIdx.x;
    if (i < N_EDGES) atomicAdd(&g_deg[dst[i]], 1);
}
__global__ void k_scan1() {
    __shared__ int sh[SCAN_B];
    int t = threadIdx.x, b = blockIdx.x;
    int i = b * SCAN_B + t;
    int v = (i < N_NODES) ? g_deg[i] : 0;
    sh[t] = v;
    __syncthreads();
    for (int s = 1; s < SCAN_B; s <<= 1) {
        int u = (t >= s) ? sh[t - s] : 0;
        __syncthreads();
        sh[t] += u;
        __syncthreads();
    }
    if (i < N_NODES) g_off[i + 1] = sh[t];
    if (t == SCAN_B - 1) g_bsum[b] = sh[t];
}
__global__ void k_scan2() {
    int acc = 0;
    for (int b = 0; b < SCAN_NB; ++b) { g_carry[b] = acc; acc += g_bsum[b]; }
}
__global__ void k_scan3() {
    int t = threadIdx.x, b = blockIdx.x;
    int i = b * SCAN_B + t;
    if (i < N_NODES) g_off[i + 1] += g_carry[b];
    if (i == 0) g_off[0] = 0;
}
__global__ void k_fill(const int* __restrict__ src, const int* __restrict__ dst,
                       const float* __restrict__ w) {
    int i = blockIdx.x * blockDim.x + threadIdx.x;
    if (i < N_EDGES) {
        int d = dst[i];
        int p = atomicAdd(&g_cursor[d], 1);
        g_edge[p] = make_uint2((unsigned)src[i], __float_as_uint(w[i]));
    }
}

/* ---------------- weight prep: fp32 W[k][n] -> fp16 [n][k] ---------------- */
__global__ void k_wprep(const float* __restrict__ W1a, const float* __restrict__ W1b) {
    int idx = blockIdx.x * blockDim.x + threadIdx.x;
    if (idx >= 2 * NPAD * FH) return;
    int branch = idx / (NPAD * FH);
    int rem = idx - branch * NPAD * FH;
    int n = rem / FH, k = rem - n * FH;
    const float* W = branch ? W1b : W1a;
    float w = (n < HID) ? W[k * HID + n] : 0.f;
    g_Wf[idx] = __float2half_rn(w);
}

/* ---------------- mma.sync fp16 GEMM: H = x(:,768 slice) @ W1 ---------------- */
#define A_ST  80
#define B_ST  80
#define ASZ   (128 * A_ST)
#define BSZ   (NPAD * B_ST)
#define OFF_A(s) ((s) * ASZ)
#define OFF_B(s) (2 * ASZ + (s) * BSZ)
#define GEMM_SMEM (2 * ASZ + 2 * BSZ)   /* 53760 B */

__global__ void __launch_bounds__(256) k_gemm_mma(const float* __restrict__ x) {
    extern __shared__ char smem[];
    const uint32_t sb = smem_u32(smem);
    const int tid  = threadIdx.x;
    const int wid  = tid >> 5, lane = tid & 31;
    const int wm   = wid >> 1;
    const int wn   = wid & 1;
    const int branch = blockIdx.y;
    const int row0 = blockIdx.x * 128;

    const __half* __restrict__ Wf = g_Wf + (size_t)branch * NPAD * FH;
    const float* __restrict__ xb = x + (size_t)branch * FH;

    float acc[2][13][4];
#pragma unroll
    for (int i = 0; i < 2; ++i)
#pragma unroll
        for (int j = 0; j < 13; ++j)
#pragma unroll
            for (int q = 0; q < 4; ++q) acc[i][j][q] = 0.f;

    const int a_row = tid >> 1;
    const int a_kof = (tid & 1) * 16;
    const int a_rg  = row0 + a_row;
    const bool a_ok = (a_rg < N_NODES);
    const float* a_src_base = xb + (size_t)a_rg * FEAT + a_kof;
    const uint32_t a_smem_byte = a_row * A_ST + a_kof * 2;

    auto issue_B = [&](int kb, int s) {
#pragma unroll
        for (int it = 0; it < 4; ++it) {
            int idx = tid + it * 256;
            if (idx < NPAD * 4) {
                int n = idx >> 2, c = idx & 3;
                uint32_t off = n * B_ST + c * 16;
                const char* sg = (const char*)(Wf + (size_t)n * FH + kb) + c * 16;
                cp_async16(sb + OFF_B(s) + off, sg);
            }
        }
        CP_COMMIT();
    };

    auto store_A = [&](const float4* v, int s) {
        char* ah = smem + OFF_A(s) + a_smem_byte;
#pragma unroll
        for (int i = 0; i < 4; ++i) {
            float4 f = v[i];
            __half2 h01 = __floats2half2_rn(f.x, f.y);
            __half2 h23 = __floats2half2_rn(f.z, f.w);
            *(uint2*)(ah + i * 8) = make_uint2(*(uint32_t*)&h01, *(uint32_t*)&h23);
        }
    };

    /* x4 lane mapping (A and B identical pattern): rows +8 for lanes 16-31,
       kbyte +16 for lanes 8-15 / 24-31 */
    const uint32_t ld4_row = (lane & 7) + ((lane >> 4) & 1) * 8;
    const uint32_t ld4_kb  = ((lane >> 3) & 1) * 16;
    /* x2 (lanes 0-15): rows lane&7, kb +16 for lanes 8-15 */
    const uint32_t ld2_row = lane & 7;
    const uint32_t ld2_kb  = ((lane >> 3) & 1) * 16;
    /* A x4 (m16 fragment): rows 0-7 lanes 0-7, rows 8-15 lanes 8-15, kb+16 lanes 16-31 */
    const uint32_t a_ld_row = (lane & 7) + ((lane >> 3) & 1) * 8;
    const uint32_t a_ld_kb  = ((lane >> 4) & 1) * 16;

    {
        float4 av[4];
#pragma unroll
        for (int i = 0; i < 4; ++i)
            av[i] = a_ok ? *(const float4*)(a_src_base + i * 4)
                         : make_float4(0.f, 0.f, 0.f, 0.f);
        issue_B(0, 0);
        store_A(av, 0);
        CP_WAIT0();
    }
    __syncthreads();

    for (int kb = 0; kb < 24; ++kb) {
        const int s = kb & 1;
        float4 av[4];
        const bool more = (kb < 23);
        if (more) {
#pragma unroll
            for (int i = 0; i < 4; ++i)
                av[i] = a_ok ? *(const float4*)(a_src_base + (kb + 1) * 32 + i * 4)
                             : make_float4(0.f, 0.f, 0.f, 0.f);
            issue_B((kb + 1) * 32, s ^ 1);
        }

        const uint32_t baseA = sb + OFF_A(s);
        const uint32_t baseB = sb + OFF_B(s);
#pragma unroll
        for (int ks = 0; ks < 2; ++ks) {
            uint32_t ah[2][4];
#pragma unroll
            for (int mt = 0; mt < 2; ++mt) {
                uint32_t r = wm * 32 + mt * 16 + a_ld_row;
                uint32_t ab = r * A_ST + ks * 32 + a_ld_kb;
                ldsm_x4(baseA + ab, ah[mt][0], ah[mt][1], ah[mt][2], ah[mt][3]);
            }
            /* 6 paired x4 B loads cover nt = 0..11 */
#pragma unroll
            for (int ntp = 0; ntp < 6; ++ntp) {
                uint32_t n = wn * 104 + ntp * 16 + ld4_row;
                uint32_t bb = n * B_ST + ks * 32 + ld4_kb;
                uint32_t b0, b1, b2, b3;
                ldsm_x4(baseB + bb, b0, b1, b2, b3);
                mma_f16(acc[0][2 * ntp],     ah[0], b0, b1);
                mma_f16(acc[1][2 * ntp],     ah[1], b0, b1);
                mma_f16(acc[0][2 * ntp + 1], ah[0], b2, b3);
                mma_f16(acc[1][2 * ntp + 1], ah[1], b2, b3);
            }
            /* tail nt = 12 */
            {
                uint32_t n = wn * 104 + 96 + ld2_row;
                uint32_t bb = n * B_ST + ks * 32 + ld2_kb;
                uint32_t b0, b1;
                ldsm_x2(baseB + bb, b0, b1);
                mma_f16(acc[0][12], ah[0], b0, b1);
                mma_f16(acc[1][12], ah[1], b0, b1);
            }
        }

        if (more) {
            store_A(av, s ^ 1);
            CP_WAIT0();
        }
        __syncthreads();
    }

    /* ---- epilogue: regs -> g_Hh (fp16) ---- */
#pragma unroll
    for (int mt = 0; mt < 2; ++mt) {
        int r0g = row0 + wm * 32 + mt * 16 + (lane >> 2);
#pragma unroll
        for (int nt = 0; nt < 13; ++nt) {
            int col = wn * 104 + nt * 8 + (lane & 3) * 2;
            if (col < HID) {
                __half2 h01 = __floats2half2_rn(acc[mt][nt][0], acc[mt][nt][1]);
                __half2 h23 = __floats2half2_rn(acc[mt][nt][2], acc[mt][nt][3]);
                if (r0g < N_NODES)
                    *(__half2*)(g_Hh + (size_t)r0g * HB + branch * HID + col) = h01;
                if (r0g + 8 < N_NODES)
                    *(__half2*)(g_Hh + (size_t)(r0g + 8) * HB + branch * HID + col) = h23;
            }
        }
    }
}

/* ---------------- fused layer-1 SpMM + bias + relu + 200->2 ---------------- */
__device__ __forceinline__ void acc8(float* a, uint4 p, float w) {
    const __half2* h = (const __half2*)&p;
#pragma unroll
    for (int i = 0; i < 4; ++i) {
        float2 f = __half22float2(h[i]);
        a[2 * i]     += w * f.x;
        a[2 * i + 1] += w * f.y;
    }
}

__global__ void __launch_bounds__(256) k_spmm_fused(const float* __restrict__ b1a,
                                                    const float* __restrict__ b1b,
                                                    const float* __restrict__ W2a,
                                                    const float* __restrict__ W2b) {
    const int wid = threadIdx.x >> 5, lane = threadIdx.x & 31;
    const int n = blockIdx.x * 8 + wid;
    if (n >= N_NODES) return;

    float acc[16];
#pragma unroll
    for (int i = 0; i < 16; ++i) acc[i] = 0.f;

    const int e0 = g_off[n], e1 = g_off[n + 1];
    const uint4* __restrict__ Hq = (const uint4*)g_Hh;

    if (lane < 25) {
        const int base = lane * 2;
        int j = e0;
        for (; j + 1 < e1; j += 2) {
            uint2 ed0 = __ldg(&g_edge[j]);
            uint2 ed1 = __ldg(&g_edge[j + 1]);
            float w0 = __uint_as_float(ed0.y);
            float w1 = __uint_as_float(ed1.y);
            uint4 p0 = Hq[(size_t)ed0.x * 50 + base];
            uint4 q0 = Hq[(size_t)ed0.x * 50 + base + 1];
            uint4 p1 = Hq[(size_t)ed1.x * 50 + base];
            uint4 q1 = Hq[(size_t)ed1.x * 50 + base + 1];
            acc8(acc,     p0, w0);
            acc8(acc + 8, q0, w0);
            acc8(acc,     p1, w1);
            acc8(acc + 8, q1, w1);
        }
        if (j < e1) {
            uint2 ed0 = __ldg(&g_edge[j]);
            float w0 = __uint_as_float(ed0.y);
            uint4 p0 = Hq[(size_t)ed0.x * 50 + base];
            uint4 q0 = Hq[(size_t)ed0.x * 50 + base + 1];
            acc8(acc,     p0, w0);
            acc8(acc + 8, q0, w0);
        }
    }

    float za0 = 0.f, za1 = 0.f, zb0 = 0.f, zb1 = 0.f;
    if (lane < 25) {
#pragma unroll
        for (int c = 0; c < 16; ++c) {
            int col = lane * 16 + c;
            bool bB = (col >= HID);
            int hid = bB ? col - HID : col;
            float v = acc[c] + __ldg(bB ? &b1b[hid] : &b1a[hid]);
            v = fmaxf(v, 0.f);
            const float* __restrict__ W2 = bB ? W2b : W2a;
            float w0 = __ldg(&W2[hid * 2 + 0]);
            float w1 = __ldg(&W2[hid * 2 + 1]);
            if (bB) { zb0 += v * w0; zb1 += v * w1; }
            else    { za0 += v * w0; za1 += v * w1; }
        }
    }
#pragma unroll
    for (int o = 16; o; o >>= 1) {
        za0 += __shfl_xor_sync(0xffffffffu, za0, o);
        za1 += __shfl_xor_sync(0xffffffffu, za1, o);
        zb0 += __shfl_xor_sync(0xffffffffu, zb0, o);
        zb1 += __shfl_xor_sync(0xffffffffu, zb1, o);
    }
    if (lane == 0) {
        g_Z[n * 4 + 0] = za0;
        g_Z[n * 4 + 1] = za1;
        g_Z[n * 4 + 2] = zb0;
        g_Z[n * 4 + 3] = zb1;
    }
}

/* ---------------- layer-2 SpMM + softmax + vote ---------------- */
__global__ void __launch_bounds__(256) k_final(const float* __restrict__ b2a,
                                               const float* __restrict__ b2b,
                                               float* __restrict__ out) {
    int wid = threadIdx.x >> 5, lane = threadIdx.x & 31;
    int n = blockIdx.x * 8 + wid;
    if (n >= N_NODES) return;

    float s0 = 0.f, s1 = 0.f, s2 = 0.f, s3 = 0.f;
    int e0 = g_off[n], e1 = g_off[n + 1];
    const float4* __restrict__ Z4 = (const float4*)g_Z;
    for (int j = e0 + lane; j < e1; j += 32) {
        uint2 ed = __ldg(&g_edge[j]);
        float w  = __uint_as_float(ed.y);
        float4 z = Z4[ed.x];
        s0 += w * z.x;
        s1 += w * z.y;
        s2 += w * z.z;
        s3 += w * z.w;
    }
    for (int o = 16; o; o >>= 1) {
        s0 += __shfl_xor_sync(0xffffffffu, s0, o);
        s1 += __shfl_xor_sync(0xffffffffu, s1, o);
        s2 += __shfl_xor_sync(0xffffffffu, s2, o);
        s3 += __shfl_xor_sync(0xffffffffu, s3, o);
    }
    if (lane == 0) {
        float za0 = s0 + b2a[0], za1 = s1 + b2a[1];
        float m  = fmaxf(za0, za1);
        float ea0 = __expf(za0 - m), ea1 = __expf(za1 - m);
        float ia  = 1.f / (ea0 + ea1);
        float pa0 = ea0 * ia, pa1 = ea1 * ia;

        float zb0 = s2 + b2b[0], zb1 = s3 + b2b[1];
        m = fmaxf(zb0, zb1);
        float eb0 = __expf(zb0 - m), eb1 = __expf(zb1 - m);
        float ib  = 1.f / (eb0 + eb1);
        float pb0 = eb0 * ib, pb1 = eb1 * ib;

        float v0 = fmaxf(pa0, pb0), v1 = fmaxf(pa1, pb1);
        float inv = 1.f / (v0 + v1);
        out[n * 2 + 0] = v0 * inv;
        out[n * 2 + 1] = v1 * inv;
    }
}

/* ---------------- launch ---------------- */
extern "C" void kernel_launch(void* const* d_in, const int* in_sizes, int n_in,
                              void* d_out, int out_size) {
    const float* x    = (const float*)d_in[0];
    const int*   esrc = (const int*)  d_in[1];
    const int*   edst = (const int*)  d_in[2];
    const float* ew   = (const float*)d_in[3];
    const float* W1a  = (const float*)d_in[4];
    const float* b1a  = (const float*)d_in[5];
    const float* W2a  = (const float*)d_in[6];
    const float* b2a  = (const float*)d_in[7];
    const float* W1b  = (const float*)d_in[8];
    const float* b1b  = (const float*)d_in[9];
    const float* W2b  = (const float*)d_in[10];
    const float* b2b  = (const float*)d_in[11];
    float* out = (float*)d_out;

    void *p_deg = nullptr, *p_off = nullptr, *p_cursor = nullptr;
    cudaGetSymbolAddress(&p_deg, g_deg);
    cudaGetSymbolAddress(&p_off, g_off);
    cudaGetSymbolAddress(&p_cursor, g_cursor);

    cudaFuncSetAttribute(k_gemm_mma, cudaFuncAttributeMaxDynamicSharedMemorySize,
                         GEMM_SMEM);

    /* one-time host-side stream/event setup (no device allocations) */
    static cudaStream_t s2 = nullptr;
    static cudaEvent_t evF = nullptr, evJ = nullptr;
    if (!s2) {
        cudaStreamCreateWithFlags(&s2, cudaStreamNonBlocking);
        cudaEventCreateWithFlags(&evF, cudaEventDisableTiming);
        cudaEventCreateWithFlags(&evJ, cudaEventDisableTiming);
    }

    /* fork: CSR build on s2, GEMM path on main stream */
    cudaEventRecord(evF, 0);
    cudaStreamWaitEvent(s2, evF, 0);

    /* --- s2: CSR build --- */
    cudaMemsetAsync(p_deg, 0, N_NODES * sizeof(int), s2);
    k_count<<<(N_EDGES + 255) / 256, 256, 0, s2>>>(edst);
    k_scan1<<<SCAN_NB, SCAN_B, 0, s2>>>();
    k_scan2<<<1, 1, 0, s2>>>();
    k_scan3<<<SCAN_NB, SCAN_B, 0, s2>>>();
    cudaMemcpyAsync(p_cursor, p_off, N_NODES * sizeof(int),
                    cudaMemcpyDeviceToDevice, s2);
    k_fill<<<(N_EDGES + 255) / 256, 256, 0, s2>>>(esrc, edst, ew);
    cudaEventRecord(evJ, s2);

    /* --- main: weight prep + tensor-core layer-1 GEMM (both branches) --- */
    k_wprep<<<(2 * NPAD * FH + 255) / 256, 256>>>(W1a, W1b);
    k_gemm_mma<<<dim3((N_NODES + 127) / 128, 2), 256, GEMM_SMEM>>>(x);

    /* join, then fused graph conv + hidden layer, layer-2 + vote */
    cudaStreamWaitEvent(0, evJ, 0);
    k_spmm_fused<<<(N_NODES + 7) / 8, 256>>>(b1a, b1b, W2a, W2b);
    k_final<<<(N_NODES + 7) / 8, 256>>>(b2a, b2b, out);
}

// round 12
// speedup vs baseline: 2.8973x; 1.1089x over previous
#include <cuda_runtime.h>
#include <cuda_bf16.h>
#include <cuda_fp16.h>
#include <cstdint>
#include <cstddef>

#define N_NODES 50000
#define N_EDGES 1600000
#define FEAT    1536
#define FH      768
#define HID     200
#define HB      400
#define NPAD    208

/* ---------------- scratch ---------------- */
__device__ __half g_Hh[(size_t)N_NODES * HB];   /* x @ W1 in fp16 (40 MB) */
__device__ float g_Z  [N_NODES * 4];
__device__ int   g_deg   [N_NODES];
__device__ int   g_off   [N_NODES + 1];
__device__ int   g_cursor[N_NODES];
__device__ uint2 g_edge  [N_EDGES];             /* packed (src, w) */
/* pre-transposed fp16 weights: [branch][n=208][k=768] */
__device__ __half g_Wf[2 * NPAD * FH];

/* ---------------- small PTX helpers ---------------- */
__device__ __forceinline__ uint32_t smem_u32(const void* p) {
    uint32_t a;
    asm("{ .reg .u64 t; cvta.to.shared.u64 t, %1; cvt.u32.u64 %0, t; }"
        : "=r"(a) : "l"(p));
    return a;
}
__device__ __forceinline__ void cp_async16(uint32_t dst, const void* src) {
    asm volatile("cp.async.cg.shared.global [%0], [%1], 16;"
                 :: "r"(dst), "l"(src) : "memory");
}
#define CP_COMMIT() asm volatile("cp.async.commit_group;" ::: "memory")
#define CP_WAIT0()  asm volatile("cp.async.wait_group 0;" ::: "memory")
#define CP_WAIT1()  asm volatile("cp.async.wait_group 1;" ::: "memory")

__device__ __forceinline__ void ldsm_x4(uint32_t a, uint32_t& r0, uint32_t& r1,
                                        uint32_t& r2, uint32_t& r3) {
    asm volatile("ldmatrix.sync.aligned.m8n8.x4.shared.b16 {%0,%1,%2,%3}, [%4];"
                 : "=r"(r0), "=r"(r1), "=r"(r2), "=r"(r3) : "r"(a));
}
__device__ __forceinline__ void ldsm_x2(uint32_t a, uint32_t& r0, uint32_t& r1) {
    asm volatile("ldmatrix.sync.aligned.m8n8.x2.shared.b16 {%0,%1}, [%2];"
                 : "=r"(r0), "=r"(r1) : "r"(a));
}
__device__ __forceinline__ void mma_f16(float* c, const uint32_t* a,
                                        uint32_t b0, uint32_t b1) {
    asm volatile(
        "mma.sync.aligned.m16n8k16.row.col.f32.f16.f16.f32 "
        "{%0,%1,%2,%3}, {%4,%5,%6,%7}, {%8,%9}, {%0,%1,%2,%3};"
        : "+f"(c[0]), "+f"(c[1]), "+f"(c[2]), "+f"(c[3])
        : "r"(a[0]), "r"(a[1]), "r"(a[2]), "r"(a[3]), "r"(b0), "r"(b1));
}
__device__ __forceinline__ uint32_t h2pack(float2 f) {
    __half2 h = __floats2half2_rn(f.x, f.y);
    return *(uint32_t*)&h;
}

/* ---------------- CSR build ---------------- */
__global__ void k_count(const int* __restrict__ dst) {
    int i = blockIdx.x * blockDim.x + threadIdx.x;
    if (i < N_EDGES) atomicAdd(&g_deg[dst[i]], 1);
}

/* single-block scan: 1024 threads x 49 contiguous elements */
__global__ void __launch_bounds__(1024) k_scan_all() {
    __shared__ int sh[1024];
    const int t = threadIdx.x;
    const int base = t * 49;
    int loc[49];
    int sum = 0;
#pragma unroll
    for (int i = 0; i < 49; ++i) {
        int idx = base + i;
        int v = (idx < N_NODES) ? g_deg[idx] : 0;
        loc[i] = sum;
        sum += v;
    }
    sh[t] = sum;
    __syncthreads();
    for (int s = 1; s < 1024; s <<= 1) {
        int u = (t >= s) ? sh[t - s] : 0;
        __syncthreads();
        sh[t] += u;
        __syncthreads();
    }
    int carry = (t == 0) ? 0 : sh[t - 1];
#pragma unroll
    for (int i = 0; i < 49; ++i) {
        int idx = base + i;
        if (idx < N_NODES) g_off[idx] = carry + loc[i];
    }
    if (t == 1023) g_off[N_NODES] = sh[1023];
}

__global__ void k_fill(const int* __restrict__ src, const int* __restrict__ dst,
                       const float* __restrict__ w) {
    int i = blockIdx.x * blockDim.x + threadIdx.x;
    if (i < N_EDGES) {
        int d = dst[i];
        int p = atomicAdd(&g_cursor[d], 1);
        g_edge[p] = make_uint2((unsigned)src[i], __float_as_uint(w[i]));
    }
}

/* ---------------- weight prep: fp32 W[k][n] -> fp16 [n][k] ---------------- */
__global__ void k_wprep(const float* __restrict__ W1a, const float* __restrict__ W1b) {
    int idx = blockIdx.x * blockDim.x + threadIdx.x;
    if (idx >= 2 * NPAD * FH) return;
    int branch = idx / (NPAD * FH);
    int rem = idx - branch * NPAD * FH;
    int n = rem / FH, k = rem - n * FH;
    const float* W = branch ? W1b : W1a;
    float w = (n < HID) ? W[k * HID + n] : 0.f;
    g_Wf[idx] = __float2half_rn(w);
}

/* ---------------- mma.sync fp16 GEMM v3: H = x(:,768 slice) @ W1 ----------------
 * CTA tile M=128, N=208, BK=64 (12 iterations), double-buffered cp.async.
 * A kept as raw fp32 in SMEM (cp.async, no conversion pass); fragments built
 * via LDS.64 + cvt in the consumer. B (pre-converted fp16) streamed via cp.async.
 */
#define A_STB 272                 /* 64 fp32 = 256B + 16 pad */
#define B_STB 144                 /* 64 fp16 = 128B + 16 pad */
#define ASZ3  (128 * A_STB)       /* 34816 */
#define BSZ3  (NPAD * B_STB)      /* 29952 */
#define OFF_A3(s) ((s) * ASZ3)
#define OFF_B3(s) (2 * ASZ3 + (s) * BSZ3)
#define GEMM_SMEM (2 * ASZ3 + 2 * BSZ3)   /* 129536 B */

__global__ void __launch_bounds__(256) k_gemm_mma(const float* __restrict__ x) {
    extern __shared__ char smem[];
    const uint32_t sb = smem_u32(smem);
    const int tid  = threadIdx.x;
    const int wid  = tid >> 5, lane = tid & 31;
    const int wm   = wid >> 1;            /* 0..3: 32-row sub-tile */
    const int wn   = wid & 1;             /* 0..1: 104-col sub-tile */
    const int branch = blockIdx.y;
    const int row0 = blockIdx.x * 128;

    const __half* __restrict__ Wf = g_Wf + (size_t)branch * NPAD * FH;
    const float* __restrict__ xb = x + (size_t)branch * FH;

    float acc[2][13][4];
#pragma unroll
    for (int i = 0; i < 2; ++i)
#pragma unroll
        for (int j = 0; j < 13; ++j)
#pragma unroll
            for (int q = 0; q < 4; ++q) acc[i][j][q] = 0.f;

    auto issue_stage = [&](int kb, int s) {
        /* A: 128 rows x 64 fp32 = 2048 16B-chunks, 8 per thread */
#pragma unroll
        for (int it = 0; it < 8; ++it) {
            int idx = tid + it * 256;
            int r = idx >> 4, c = idx & 15;
            if (row0 + r < N_NODES)
                cp_async16(sb + OFF_A3(s) + r * A_STB + c * 16,
                           xb + (size_t)(row0 + r) * FEAT + kb + c * 4);
        }
        /* B: 208 rows x 128B = 1664 chunks, <=7 per thread */
#pragma unroll
        for (int it = 0; it < 7; ++it) {
            int idx = tid + it * 256;
            if (idx < NPAD * 8) {
                int n = idx >> 3, c = idx & 7;
                cp_async16(sb + OFF_B3(s) + n * B_STB + c * 16,
                           (const char*)(Wf + (size_t)n * FH + kb) + c * 16);
            }
        }
        CP_COMMIT();
    };

    /* B ldsm lane mapping */
    const uint32_t ld4_row = (lane & 7) + ((lane >> 4) & 1) * 8;
    const uint32_t ld4_kb  = ((lane >> 3) & 1) * 16;
    const uint32_t ld2_row = lane & 7;
    const uint32_t ld2_kb  = ((lane >> 3) & 1) * 16;
    /* A fragment LDS base (lane part): row lane>>2, k-words (lane&3)*2 */
    const uint32_t a_r  = lane >> 2;
    const uint32_t a_kw = (lane & 3) * 2;

    issue_stage(0, 0);

    for (int kb = 0; kb < 12; ++kb) {
        const int s = kb & 1;
        const bool more = (kb < 11);
        if (more) {
            issue_stage((kb + 1) * 64, s ^ 1);
            CP_WAIT1();
        } else {
            CP_WAIT0();
        }
        __syncthreads();

        const uint32_t baseB = sb + OFF_B3(s);
#pragma unroll
        for (int ks = 0; ks < 4; ++ks) {
            uint32_t ah[2][4];
#pragma unroll
            for (int mt = 0; mt < 2; ++mt) {
                const char* ap = smem + OFF_A3(s)
                               + (wm * 32 + mt * 16 + a_r) * A_STB
                               + (ks * 16 + a_kw) * 4;
                float2 f0 = *(const float2*)(ap);
                float2 f1 = *(const float2*)(ap + 8 * A_STB);
                float2 f2 = *(const float2*)(ap + 32);
                float2 f3 = *(const float2*)(ap + 8 * A_STB + 32);
                ah[mt][0] = h2pack(f0);
                ah[mt][1] = h2pack(f1);
                ah[mt][2] = h2pack(f2);
                ah[mt][3] = h2pack(f3);
            }
#pragma unroll
            for (int ntp = 0; ntp < 6; ++ntp) {
                uint32_t n = wn * 104 + ntp * 16 + ld4_row;
                uint32_t bb = n * B_STB + ks * 32 + ld4_kb;
                uint32_t b0, b1, b2, b3;
                ldsm_x4(baseB + bb, b0, b1, b2, b3);
                mma_f16(acc[0][2 * ntp],     ah[0], b0, b1);
                mma_f16(acc[1][2 * ntp],     ah[1], b0, b1);
                mma_f16(acc[0][2 * ntp + 1], ah[0], b2, b3);
                mma_f16(acc[1][2 * ntp + 1], ah[1], b2, b3);
            }
            {
                uint32_t n = wn * 104 + 96 + ld2_row;
                uint32_t bb = n * B_STB + ks * 32 + ld2_kb;
                uint32_t b0, b1;
                ldsm_x2(baseB + bb, b0, b1);
                mma_f16(acc[0][12], ah[0], b0, b1);
                mma_f16(acc[1][12], ah[1], b0, b1);
            }
        }
        __syncthreads();
    }

    /* ---- epilogue: regs -> g_Hh (fp16) ---- */
#pragma unroll
    for (int mt = 0; mt < 2; ++mt) {
        int r0g = row0 + wm * 32 + mt * 16 + (lane >> 2);
#pragma unroll
        for (int nt = 0; nt < 13; ++nt) {
            int col = wn * 104 + nt * 8 + (lane & 3) * 2;
            if (col < HID) {
                __half2 h01 = __floats2half2_rn(acc[mt][nt][0], acc[mt][nt][1]);
                __half2 h23 = __floats2half2_rn(acc[mt][nt][2], acc[mt][nt][3]);
                if (r0g < N_NODES)
                    *(__half2*)(g_Hh + (size_t)r0g * HB + branch * HID + col) = h01;
                if (r0g + 8 < N_NODES)
                    *(__half2*)(g_Hh + (size_t)(r0g + 8) * HB + branch * HID + col) = h23;
            }
        }
    }
}

/* ---------------- fused layer-1 SpMM + bias + relu + 200->2 ---------------- */
__device__ __forceinline__ void acc8(float* a, uint4 p, float w) {
    const __half2* h = (const __half2*)&p;
#pragma unroll
    for (int i = 0; i < 4; ++i) {
        float2 f = __half22float2(h[i]);
        a[2 * i]     += w * f.x;
        a[2 * i + 1] += w * f.y;
    }
}

__global__ void __launch_bounds__(256) k_spmm_fused(const float* __restrict__ b1a,
                                                    const float* __restrict__ b1b,
                                                    const float* __restrict__ W2a,
                                                    const float* __restrict__ W2b) {
    const int wid = threadIdx.x >> 5, lane = threadIdx.x & 31;
    const int n = blockIdx.x * 8 + wid;
    if (n >= N_NODES) return;

    float acc[16];
#pragma unroll
    for (int i = 0; i < 16; ++i) acc[i] = 0.f;

    const int e0 = g_off[n], e1 = g_off[n + 1];
    const uint4* __restrict__ Hq = (const uint4*)g_Hh;

    if (lane < 25) {
        const int base = lane * 2;
        int j = e0;
        for (; j + 1 < e1; j += 2) {
            uint2 ed0 = __ldg(&g_edge[j]);
            uint2 ed1 = __ldg(&g_edge[j + 1]);
            float w0 = __uint_as_float(ed0.y);
            float w1 = __uint_as_float(ed1.y);
            uint4 p0 = Hq[(size_t)ed0.x * 50 + base];
            uint4 q0 = Hq[(size_t)ed0.x * 50 + base + 1];
            uint4 p1 = Hq[(size_t)ed1.x * 50 + base];
            uint4 q1 = Hq[(size_t)ed1.x * 50 + base + 1];
            acc8(acc,     p0, w0);
            acc8(acc + 8, q0, w0);
            acc8(acc,     p1, w1);
            acc8(acc + 8, q1, w1);
        }
        if (j < e1) {
            uint2 ed0 = __ldg(&g_edge[j]);
            float w0 = __uint_as_float(ed0.y);
            uint4 p0 = Hq[(size_t)ed0.x * 50 + base];
            uint4 q0 = Hq[(size_t)ed0.x * 50 + base + 1];
            acc8(acc,     p0, w0);
            acc8(acc + 8, q0, w0);
        }
    }

    float za0 = 0.f, za1 = 0.f, zb0 = 0.f, zb1 = 0.f;
    if (lane < 25) {
#pragma unroll
        for (int c = 0; c < 16; ++c) {
            int col = lane * 16 + c;
            bool bB = (col >= HID);
            int hid = bB ? col - HID : col;
            float v = acc[c] + __ldg(bB ? &b1b[hid] : &b1a[hid]);
            v = fmaxf(v, 0.f);
            const float* __restrict__ W2 = bB ? W2b : W2a;
            float w0 = __ldg(&W2[hid * 2 + 0]);
            float w1 = __ldg(&W2[hid * 2 + 1]);
            if (bB) { zb0 += v * w0; zb1 += v * w1; }
            else    { za0 += v * w0; za1 += v * w1; }
        }
    }
#pragma unroll
    for (int o = 16; o; o >>= 1) {
        za0 += __shfl_xor_sync(0xffffffffu, za0, o);
        za1 += __shfl_xor_sync(0xffffffffu, za1, o);
        zb0 += __shfl_xor_sync(0xffffffffu, zb0, o);
        zb1 += __shfl_xor_sync(0xffffffffu, zb1, o);
    }
    if (lane == 0) {
        g_Z[n * 4 + 0] = za0;
        g_Z[n * 4 + 1] = za1;
        g_Z[n * 4 + 2] = zb0;
        g_Z[n * 4 + 3] = zb1;
    }
}

/* ---------------- layer-2 SpMM + softmax + vote ---------------- */
__global__ void __launch_bounds__(256) k_final(const float* __restrict__ b2a,
                                               const float* __restrict__ b2b,
                                               float* __restrict__ out) {
    int wid = threadIdx.x >> 5, lane = threadIdx.x & 31;
    int n = blockIdx.x * 8 + wid;
    if (n >= N_NODES) return;

    float s0 = 0.f, s1 = 0.f, s2 = 0.f, s3 = 0.f;
    int e0 = g_off[n], e1 = g_off[n + 1];
    const float4* __restrict__ Z4 = (const float4*)g_Z;
    for (int j = e0 + lane; j < e1; j += 32) {
        uint2 ed = __ldg(&g_edge[j]);
        float w  = __uint_as_float(ed.y);
        float4 z = Z4[ed.x];
        s0 += w * z.x;
        s1 += w * z.y;
        s2 += w * z.z;
        s3 += w * z.w;
    }
    for (int o = 16; o; o >>= 1) {
        s0 += __shfl_xor_sync(0xffffffffu, s0, o);
        s1 += __shfl_xor_sync(0xffffffffu, s1, o);
        s2 += __shfl_xor_sync(0xffffffffu, s2, o);
        s3 += __shfl_xor_sync(0xffffffffu, s3, o);
    }
    if (lane == 0) {
        float za0 = s0 + b2a[0], za1 = s1 + b2a[1];
        float m  = fmaxf(za0, za1);
        float ea0 = __expf(za0 - m), ea1 = __expf(za1 - m);
        float ia  = 1.f / (ea0 + ea1);
        float pa0 = ea0 * ia, pa1 = ea1 * ia;

        float zb0 = s2 + b2b[0], zb1 = s3 + b2b[1];
        m = fmaxf(zb0, zb1);
        float eb0 = __expf(zb0 - m), eb1 = __expf(zb1 - m);
        float ib  = 1.f / (eb0 + eb1);
        float pb0 = eb0 * ib, pb1 = eb1 * ib;

        float v0 = fmaxf(pa0, pb0), v1 = fmaxf(pa1, pb1);
        float inv = 1.f / (v0 + v1);
        out[n * 2 + 0] = v0 * inv;
        out[n * 2 + 1] = v1 * inv;
    }
}

/* ---------------- launch ---------------- */
extern "C" void kernel_launch(void* const* d_in, const int* in_sizes, int n_in,
                              void* d_out, int out_size) {
    const float* x    = (const float*)d_in[0];
    const int*   esrc = (const int*)  d_in[1];
    const int*   edst = (const int*)  d_in[2];
    const float* ew   = (const float*)d_in[3];
    const float* W1a  = (const float*)d_in[4];
    const float* b1a  = (const float*)d_in[5];
    const float* W2a  = (const float*)d_in[6];
    const float* b2a  = (const float*)d_in[7];
    const float* W1b  = (const float*)d_in[8];
    const float* b1b  = (const float*)d_in[9];
    const float* W2b  = (const float*)d_in[10];
    const float* b2b  = (const float*)d_in[11];
    float* out = (float*)d_out;

    void *p_deg = nullptr, *p_off = nullptr, *p_cursor = nullptr;
    cudaGetSymbolAddress(&p_deg, g_deg);
    cudaGetSymbolAddress(&p_off, g_off);
    cudaGetSymbolAddress(&p_cursor, g_cursor);

    cudaFuncSetAttribute(k_gemm_mma, cudaFuncAttributeMaxDynamicSharedMemorySize,
                         GEMM_SMEM);

    static cudaStream_t s2 = nullptr;
    static cudaEvent_t evF = nullptr, evJ = nullptr;
    if (!s2) {
        cudaStreamCreateWithFlags(&s2, cudaStreamNonBlocking);
        cudaEventCreateWithFlags(&evF, cudaEventDisableTiming);
        cudaEventCreateWithFlags(&evJ, cudaEventDisableTiming);
    }

    /* #1: weight prep (main) */
    k_wprep<<<(2 * NPAD * FH + 255) / 256, 256>>>(W1a, W1b);

    /* fork CSR onto s2 */
    cudaEventRecord(evF, 0);
    cudaStreamWaitEvent(s2, evF, 0);
    cudaMemsetAsync(p_deg, 0, N_NODES * sizeof(int), s2);        /* #2 */
    k_count<<<(N_EDGES + 255) / 256, 256, 0, s2>>>(edst);        /* #3 */
    k_scan_all<<<1, 1024, 0, s2>>>();                            /* #4 */

    /* #5: tensor-core layer-1 GEMM (main, both branches) */
    k_gemm_mma<<<dim3((N_NODES + 127) / 128, 2), 256, GEMM_SMEM>>>(x);

    cudaMemcpyAsync(p_cursor, p_off, N_NODES * sizeof(int),
                    cudaMemcpyDeviceToDevice, s2);
    k_fill<<<(N_EDGES + 255) / 256, 256, 0, s2>>>(esrc, edst, ew); /* #6 */
    cudaEventRecord(evJ, s2);

    /* join, then fused graph conv + hidden layer, layer-2 + vote */
    cudaStreamWaitEvent(0, evJ, 0);
    k_spmm_fused<<<(N_NODES + 7) / 8, 256>>>(b1a, b1b, W2a, W2b);
    k_final<<<(N_NODES + 7) / 8, 256>>>(b2a, b2b, out);
}